// round 2
// baseline (speedup 1.0000x reference)
#include <cuda_runtime.h>
#include <cuda_bf16.h>
#include <math.h>

// Problem constants
#define B_  2
#define S_  2048
#define HID 2048
#define NH  16
#define NKV 4
#define DH  128
#define MROWS (B_ * S_)        // 4096
#define EPS 1e-6f

// ---------------- scratch (static device allocations are allowed) ----------------
__device__ float g_Q[(size_t)MROWS * NH * DH];   // 4096 x 2048
__device__ float g_K[(size_t)MROWS * NKV * DH];  // 4096 x 512
__device__ float g_V[(size_t)MROWS * NKV * DH];  // 4096 x 512
__device__ float g_O[(size_t)MROWS * NH * DH];   // 4096 x 2048

// ---------------- generic SGEMM: C[M,N] = A[M,K] @ B[K,N], all row-major ----------------
// BM=BN=128, BK=8, 256 threads, 8x8 per-thread micro-tile.
// Requires M%128==0, N%128==0, K%8==0 (true for all our shapes).
__global__ void __launch_bounds__(256) sgemm_kernel(
    const float* __restrict__ A, const float* __restrict__ Bm, float* __restrict__ C,
    int M, int N, int K)
{
    __shared__ float As[8][128];
    __shared__ float Bs[8][128];

    const int tid = threadIdx.x;
    const int bm = blockIdx.y * 128;
    const int bn = blockIdx.x * 128;
    const int tr = tid >> 4;        // 0..15
    const int tc = tid & 15;        // 0..15

    float acc[8][8];
#pragma unroll
    for (int i = 0; i < 8; i++)
#pragma unroll
        for (int j = 0; j < 8; j++) acc[i][j] = 0.f;

    const int ar  = tid >> 1;       // 0..127
    const int ac4 = tid & 1;        // 0..1
    const int br  = tid >> 5;       // 0..7
    const int bc4 = tid & 31;       // 0..31

    for (int k0 = 0; k0 < K; k0 += 8) {
        // Load A tile (128x8) transposed into As[k][m]
        float4 av = *(const float4*)(A + (size_t)(bm + ar) * K + k0 + ac4 * 4);
        As[ac4 * 4 + 0][ar] = av.x;
        As[ac4 * 4 + 1][ar] = av.y;
        As[ac4 * 4 + 2][ar] = av.z;
        As[ac4 * 4 + 3][ar] = av.w;
        // Load B tile (8x128)
        *(float4*)(&Bs[br][bc4 * 4]) =
            *(const float4*)(Bm + (size_t)(k0 + br) * N + bn + bc4 * 4);
        __syncthreads();

#pragma unroll
        for (int k = 0; k < 8; k++) {
            float ra[8], rb[8];
            float4 a0 = *(const float4*)(&As[k][tr * 8]);
            float4 a1 = *(const float4*)(&As[k][tr * 8 + 4]);
            float4 b0 = *(const float4*)(&Bs[k][tc * 8]);
            float4 b1 = *(const float4*)(&Bs[k][tc * 8 + 4]);
            ra[0]=a0.x; ra[1]=a0.y; ra[2]=a0.z; ra[3]=a0.w;
            ra[4]=a1.x; ra[5]=a1.y; ra[6]=a1.z; ra[7]=a1.w;
            rb[0]=b0.x; rb[1]=b0.y; rb[2]=b0.z; rb[3]=b0.w;
            rb[4]=b1.x; rb[5]=b1.y; rb[6]=b1.z; rb[7]=b1.w;
#pragma unroll
            for (int i = 0; i < 8; i++)
#pragma unroll
                for (int j = 0; j < 8; j++)
                    acc[i][j] += ra[i] * rb[j];
        }
        __syncthreads();
    }

#pragma unroll
    for (int i = 0; i < 8; i++) {
        size_t off = (size_t)(bm + tr * 8 + i) * N + bn + tc * 8;
        float4 c0 = make_float4(acc[i][0], acc[i][1], acc[i][2], acc[i][3]);
        float4 c1 = make_float4(acc[i][4], acc[i][5], acc[i][6], acc[i][7]);
        *(float4*)(C + off)     = c0;
        *(float4*)(C + off + 4) = c1;
    }
}

// ---------------- fused RMSNorm + RoPE (in place) ----------------
// One block of 128 threads per (row, head). buf layout: [row][head][DH].
__global__ void __launch_bounds__(128) rmsrope_kernel(
    float* __restrict__ buf, const float* __restrict__ w,
    const float* __restrict__ cosb, const float* __restrict__ sinb, int nheads)
{
    const int bh  = blockIdx.x;
    const int row = bh / nheads;
    const int h   = bh - row * nheads;
    const int s   = row & (S_ - 1);
    const int d   = threadIdx.x;

    float* p = buf + ((size_t)row * nheads + h) * DH;
    float v = p[d];

    float ss = v * v;
#pragma unroll
    for (int o = 16; o > 0; o >>= 1) ss += __shfl_xor_sync(0xffffffffu, ss, o);
    __shared__ float sh[4];
    if ((d & 31) == 0) sh[d >> 5] = ss;
    __syncthreads();
    float tot = sh[0] + sh[1] + sh[2] + sh[3];
    float inv = rsqrtf(tot * (1.0f / DH) + EPS);

    int pd = d ^ 64;               // rotate_half partner
    float pv  = p[pd];
    float nv  = w[d]  * v  * inv;
    float npv = w[pd] * pv * inv;
    float c  = cosb[(size_t)s * DH + d];
    float sn = sinb[(size_t)s * DH + d];
    float out = nv * c + ((d < 64) ? -npv : npv) * sn;
    __syncthreads();               // all reads complete before in-place write
    p[d] = out;
}

// ---------------- flash attention, fp32, causal ----------------
// Grid: (S/64, NH, B). 128 threads. BM=BN=64.
// smem: Qs[128][64] (d-major), Ks[64][129], Vs[64][128], Ps[64][64]
#define KS_STRIDE 129
#define FLASH_SMEM_FLOATS (128*64 + 64*KS_STRIDE + 64*128 + 64*64)

__global__ void __launch_bounds__(128) flash_kernel(
    const float* __restrict__ Qg, const float* __restrict__ Kg,
    const float* __restrict__ Vg, float* __restrict__ Og)
{
    extern __shared__ float smem[];
    float* Qs = smem;                      // [d][m]   128*64
    float* Ks = Qs + 128 * 64;             // [n][d]   64*129
    float* Vs = Ks + 64 * KS_STRIDE;       // [n][d]   64*128
    float* Ps = Vs + 64 * 128;             // [m][n]   64*64

    const int qt  = blockIdx.x;            // q tile
    const int h   = blockIdx.y;
    const int b   = blockIdx.z;
    const int kvh = h / (NH / NKV);
    const int tid = threadIdx.x;
    const int rg  = tid >> 4;              // 0..7  -> rows rg*8..+7
    const int cg  = tid & 15;              // 0..15 -> score cols cg*4..+3, out cols cg*8..+7
    const int r0  = rg * 8;
    const int c0  = cg * 4;

    const float scale = 0.08838834764831845f;   // 1/sqrt(128)

    // Load Q tile transposed (d-major), pre-scaled
    {
        const size_t qbase = ((size_t)(b * S_ + qt * 64)) * (NH * DH) + (size_t)h * DH;
#pragma unroll
        for (int i = tid; i < 64 * 32; i += 128) {
            int m = i >> 5, d4 = i & 31;
            float4 v = *(const float4*)(Qg + qbase + (size_t)m * (NH * DH) + d4 * 4);
            Qs[(d4 * 4 + 0) * 64 + m] = v.x * scale;
            Qs[(d4 * 4 + 1) * 64 + m] = v.y * scale;
            Qs[(d4 * 4 + 2) * 64 + m] = v.z * scale;
            Qs[(d4 * 4 + 3) * 64 + m] = v.w * scale;
        }
    }

    float acc[8][8];
#pragma unroll
    for (int i = 0; i < 8; i++)
#pragma unroll
        for (int j = 0; j < 8; j++) acc[i][j] = 0.f;
    float mrow[8], lrow[8];
#pragma unroll
    for (int i = 0; i < 8; i++) { mrow[i] = -1e30f; lrow[i] = 0.f; }

    for (int kt = 0; kt <= qt; kt++) {
        // Load K (padded rows) and V tiles
        const size_t kbase = ((size_t)(b * S_ + kt * 64)) * (NKV * DH) + (size_t)kvh * DH;
#pragma unroll
        for (int i = tid; i < 64 * 32; i += 128) {
            int n = i >> 5, d4 = i & 31;
            float4 kv = *(const float4*)(Kg + kbase + (size_t)n * (NKV * DH) + d4 * 4);
            Ks[n * KS_STRIDE + d4 * 4 + 0] = kv.x;
            Ks[n * KS_STRIDE + d4 * 4 + 1] = kv.y;
            Ks[n * KS_STRIDE + d4 * 4 + 2] = kv.z;
            Ks[n * KS_STRIDE + d4 * 4 + 3] = kv.w;
            float4 vv = *(const float4*)(Vg + kbase + (size_t)n * (NKV * DH) + d4 * 4);
            *(float4*)(Vs + n * 128 + d4 * 4) = vv;
        }
        __syncthreads();

        // Scores: s[8 rows][4 cols]
        float s[8][4];
#pragma unroll
        for (int i = 0; i < 8; i++)
#pragma unroll
            for (int j = 0; j < 4; j++) s[i][j] = 0.f;

#pragma unroll 4
        for (int d = 0; d < 128; d++) {
            float4 qa = *(const float4*)(Qs + d * 64 + r0);
            float4 qb = *(const float4*)(Qs + d * 64 + r0 + 4);
            float qv[8] = {qa.x, qa.y, qa.z, qa.w, qb.x, qb.y, qb.z, qb.w};
            float kv[4];
#pragma unroll
            for (int j = 0; j < 4; j++) kv[j] = Ks[(c0 + j) * KS_STRIDE + d];
#pragma unroll
            for (int i = 0; i < 8; i++)
#pragma unroll
                for (int j = 0; j < 4; j++)
                    s[i][j] += qv[i] * kv[j];
        }

        // Causal mask on the diagonal tile
        if (kt == qt) {
#pragma unroll
            for (int i = 0; i < 8; i++)
#pragma unroll
                for (int j = 0; j < 4; j++)
                    if (c0 + j > r0 + i) s[i][j] = -1e30f;
        }

        // Online softmax update
#pragma unroll
        for (int i = 0; i < 8; i++) {
            float mx = s[i][0];
            mx = fmaxf(mx, s[i][1]); mx = fmaxf(mx, s[i][2]); mx = fmaxf(mx, s[i][3]);
#pragma unroll
            for (int o = 8; o > 0; o >>= 1)
                mx = fmaxf(mx, __shfl_xor_sync(0xffffffffu, mx, o));
            float mnew = fmaxf(mrow[i], mx);
            float f = __expf(mrow[i] - mnew);
            mrow[i] = mnew;
            float ls = 0.f;
#pragma unroll
            for (int j = 0; j < 4; j++) {
                float pj = __expf(s[i][j] - mnew);
                s[i][j] = pj;
                ls += pj;
            }
#pragma unroll
            for (int o = 8; o > 0; o >>= 1)
                ls += __shfl_xor_sync(0xffffffffu, ls, o);
            lrow[i] = lrow[i] * f + ls;
#pragma unroll
            for (int j = 0; j < 8; j++) acc[i][j] *= f;
            // stash probs
#pragma unroll
            for (int j = 0; j < 4; j++)
                Ps[(r0 + i) * 64 + c0 + j] = s[i][j];
        }
        __syncthreads();

        // acc += P @ V  (out cols cg*8..+7)
#pragma unroll 2
        for (int n = 0; n < 64; n++) {
            float4 va = *(const float4*)(Vs + n * 128 + cg * 8);
            float4 vb = *(const float4*)(Vs + n * 128 + cg * 8 + 4);
            float vv[8] = {va.x, va.y, va.z, va.w, vb.x, vb.y, vb.z, vb.w};
#pragma unroll
            for (int i = 0; i < 8; i++) {
                float p = Ps[(r0 + i) * 64 + n];
#pragma unroll
                for (int j = 0; j < 8; j++)
                    acc[i][j] += p * vv[j];
            }
        }
        __syncthreads();   // before next tile overwrites Ks/Vs/Ps
    }

    // Epilogue: divide by l, write to O [row][h*DH + col]
    const size_t obase = ((size_t)(b * S_ + qt * 64)) * (NH * DH) + (size_t)h * DH;
#pragma unroll
    for (int i = 0; i < 8; i++) {
        float invl = 1.0f / lrow[i];
        float4 o0 = make_float4(acc[i][0] * invl, acc[i][1] * invl,
                                acc[i][2] * invl, acc[i][3] * invl);
        float4 o1 = make_float4(acc[i][4] * invl, acc[i][5] * invl,
                                acc[i][6] * invl, acc[i][7] * invl);
        size_t off = obase + (size_t)(r0 + i) * (NH * DH) + cg * 8;
        *(float4*)(Og + off)     = o0;
        *(float4*)(Og + off + 4) = o1;
    }
}

// ---------------- launch ----------------
extern "C" void kernel_launch(void* const* d_in, const int* in_sizes, int n_in,
                              void* d_out, int out_size)
{
    const float* X    = (const float*)d_in[0];
    // d_in[1] = attention_mask: exact causal mask, applied analytically — unused
    const float* cosp = (const float*)d_in[2];
    const float* sinp = (const float*)d_in[3];
    const float* Wq   = (const float*)d_in[4];
    const float* Wk   = (const float*)d_in[5];
    const float* Wv   = (const float*)d_in[6];
    const float* Wo   = (const float*)d_in[7];
    const float* qnw  = (const float*)d_in[8];
    const float* knw  = (const float*)d_in[9];
    float* out = (float*)d_out;

    float *Q, *K, *V, *O;
    cudaGetSymbolAddress((void**)&Q, g_Q);
    cudaGetSymbolAddress((void**)&K, g_K);
    cudaGetSymbolAddress((void**)&V, g_V);
    cudaGetSymbolAddress((void**)&O, g_O);

    // QKV projections
    sgemm_kernel<<<dim3(NH * DH / 128, MROWS / 128), 256>>>(X, Wq, Q, MROWS, NH * DH, HID);
    sgemm_kernel<<<dim3(NKV * DH / 128, MROWS / 128), 256>>>(X, Wk, K, MROWS, NKV * DH, HID);
    sgemm_kernel<<<dim3(NKV * DH / 128, MROWS / 128), 256>>>(X, Wv, V, MROWS, NKV * DH, HID);

    // RMSNorm + RoPE
    rmsrope_kernel<<<MROWS * NH, 128>>>(Q, qnw, cosp, sinp, NH);
    rmsrope_kernel<<<MROWS * NKV, 128>>>(K, knw, cosp, sinp, NKV);

    // Flash attention
    static const size_t flash_smem = (size_t)FLASH_SMEM_FLOATS * sizeof(float);
    cudaFuncSetAttribute(flash_kernel, cudaFuncAttributeMaxDynamicSharedMemorySize,
                         (int)flash_smem);
    flash_kernel<<<dim3(S_ / 64, NH, B_), 128, flash_smem>>>(Q, K, V, O);

    // Output projection
    sgemm_kernel<<<dim3(HID / 128, MROWS / 128), 256>>>(O, Wo, out, MROWS, HID, HID);
}

// round 5
// speedup vs baseline: 1.7582x; 1.7582x over previous
#include <cuda_runtime.h>
#include <cuda_bf16.h>
#include <math.h>
#include <stdint.h>

// Problem constants
#define B_  2
#define S_  2048
#define HID 2048
#define NH  16
#define NKV 4
#define DH  128
#define MROWS (B_ * S_)        // 4096
#define EPS 1e-6f

// ---------------- scratch ----------------
__device__ float g_X [(size_t)MROWS * HID];      // tf32-rounded hidden states
__device__ float g_Q [(size_t)MROWS * NH * DH];
__device__ float g_K [(size_t)MROWS * NKV * DH];
__device__ float g_V [(size_t)MROWS * NKV * DH];
__device__ float g_O [(size_t)MROWS * NH * DH];
__device__ float g_WqT[(size_t)HID * NH * DH];   // [N][K] transposed, tf32-rounded
__device__ float g_WkT[(size_t)HID * NKV * DH];
__device__ float g_WvT[(size_t)HID * NKV * DH];
__device__ float g_WoT[(size_t)NH * DH * HID];

// ---------------- helpers ----------------
__device__ __forceinline__ uint32_t smem_u32(const void* p) {
    uint32_t a;
    asm("{ .reg .u64 t; cvta.to.shared.u64 t, %1; cvt.u32.u64 %0, t; }" : "=r"(a) : "l"(p));
    return a;
}
__device__ __forceinline__ float tf32r(float x) {
    uint32_t r;
    asm("cvt.rna.tf32.f32 %0, %1;" : "=r"(r) : "f"(x));
    return __uint_as_float(r);
}
#define CP_ASYNC16(sdst, gsrc) \
    asm volatile("cp.async.cg.shared.global [%0], [%1], 16;" :: "r"(sdst), "l"(gsrc))
#define CP_COMMIT() asm volatile("cp.async.commit_group;" ::: "memory")
#define CP_WAIT(n)  asm volatile("cp.async.wait_group %0;" :: "n"(n) : "memory")

__device__ __forceinline__ void mma_tf32(float& c0, float& c1, float& c2, float& c3,
                                         uint32_t a0, uint32_t a1, uint32_t a2, uint32_t a3,
                                         uint32_t b0, uint32_t b1) {
    asm volatile(
        "mma.sync.aligned.m16n8k8.row.col.f32.tf32.tf32.f32 "
        "{%0,%1,%2,%3}, {%4,%5,%6,%7}, {%8,%9}, {%0,%1,%2,%3};"
        : "+f"(c0), "+f"(c1), "+f"(c2), "+f"(c3)
        : "r"(a0), "r"(a1), "r"(a2), "r"(a3), "r"(b0), "r"(b1));
}

// ---------------- tf32 rounding (elementwise, in/out may alias) ----------------
__global__ void __launch_bounds__(256) tf32_round_kernel(float* __restrict__ dst,
                                                         const float* __restrict__ src,
                                                         size_t n4) {
    for (size_t i = blockIdx.x * blockDim.x + threadIdx.x; i < n4;
         i += (size_t)gridDim.x * blockDim.x) {
        float4 v = ((const float4*)src)[i];
        v.x = tf32r(v.x); v.y = tf32r(v.y); v.z = tf32r(v.z); v.w = tf32r(v.w);
        ((float4*)dst)[i] = v;
    }
}

// ---------------- transpose + tf32 round: dst[C][R] = tf32(src[R][C]) ----------------
__global__ void __launch_bounds__(256) transpose_tf32_kernel(float* __restrict__ dst,
                                                             const float* __restrict__ src,
                                                             int R, int C) {
    __shared__ float t[32][33];
    int bx = blockIdx.x * 32;     // col tile
    int by = blockIdx.y * 32;     // row tile
    int tx = threadIdx.x, ty = threadIdx.y;     // 32 x 8
#pragma unroll
    for (int i = 0; i < 4; i++)
        t[ty + i * 8][tx] = src[(size_t)(by + ty + i * 8) * C + bx + tx];
    __syncthreads();
#pragma unroll
    for (int i = 0; i < 4; i++)
        dst[(size_t)(bx + ty + i * 8) * R + by + tx] = tf32r(t[tx][ty + i * 8]);
}

// ---------------- tf32 mma.sync GEMM ----------------
// C[M,N] = A[M,2048] @ Bt[N,2048]^T.  CTA 128x128, BK=16, 3-stage cp.async.
// 8 warps as 4(m) x 2(n); warp tile 32x64.
// Smem rows padded to 20 floats (80B): fragment lds pattern is bank-conflict-free.
#define GK      2048
#define GM_BM   128
#define GM_BN   128
#define GM_BK   16
#define GM_LDS  20                          // floats per smem row
#define GM_NST  3
#define GM_NIT  (GK / GM_BK)                // 128
#define GM_STAGE_FLOATS (2 * 128 * GM_LDS)  // A tile + B tile = 5120 floats
#define GM_SMEM_BYTES (GM_NST * GM_STAGE_FLOATS * 4)   // 61440

__device__ __forceinline__ void gm_load_stage(uint32_t sA, uint32_t sB,
                                              const float* __restrict__ Atile,
                                              const float* __restrict__ Btile,
                                              int tid) {
#pragma unroll
    for (int i = 0; i < 2; i++) {           // A: 128 rows x 4 chunks of 16B
        int idx = i * 256 + tid;
        int r = idx >> 2, c = idx & 3;
        CP_ASYNC16(sA + (uint32_t)(r * (GM_LDS * 4) + c * 16),
                   Atile + (size_t)r * GK + c * 4);
    }
#pragma unroll
    for (int i = 0; i < 2; i++) {           // B: 128 rows x 4 chunks of 16B
        int idx = i * 256 + tid;
        int r = idx >> 2, c = idx & 3;
        CP_ASYNC16(sB + (uint32_t)(r * (GM_LDS * 4) + c * 16),
                   Btile + (size_t)r * GK + c * 4);
    }
    CP_COMMIT();
}

__global__ void __launch_bounds__(256, 1) gemm_tf32mma_kernel(
    const float* __restrict__ A, const float* __restrict__ Bt,
    float* __restrict__ C, int M, int N)
{
    extern __shared__ float gsm[];
    const uint32_t sbase = smem_u32(gsm);
    const int tid = threadIdx.x;
    const int wid = tid >> 5, lid = tid & 31;
    const int wm = wid >> 1;                // 0..3  -> m offset wm*32
    const int wn = wid & 1;                 // 0..1  -> n offset wn*64
    const int gid = lid >> 2;               // 0..7
    const int tig = lid & 3;                // 0..3
    const int bm = blockIdx.y * GM_BM;
    const int bn = blockIdx.x * GM_BN;

    float acc[2][8][4];
#pragma unroll
    for (int mt = 0; mt < 2; mt++)
#pragma unroll
        for (int nt = 0; nt < 8; nt++)
#pragma unroll
            for (int q = 0; q < 4; q++) acc[mt][nt][q] = 0.f;

    const float* Abase = A + (size_t)bm * GK;
    const float* Bbase = Bt + (size_t)bn * GK;

    // stage smem addresses (bytes)
    uint32_t stA[GM_NST], stB[GM_NST];
#pragma unroll
    for (int s = 0; s < GM_NST; s++) {
        stA[s] = sbase + (uint32_t)(s * GM_STAGE_FLOATS * 4);
        stB[s] = stA[s] + 128u * GM_LDS * 4u;
    }

    // prologue: load stages 0,1
    gm_load_stage(stA[0], stB[0], Abase, Bbase, tid);
    gm_load_stage(stA[1], stB[1], Abase + GM_BK, Bbase + GM_BK, tid);

    const float* As0;
    const float* Bs0;

    for (int it = 0; it < GM_NIT; it++) {
        CP_WAIT(1);
        __syncthreads();

        const int ki = it + 2;
        if (ki < GM_NIT) {
            const int b = ki % GM_NST;
            gm_load_stage(stA[b], stB[b], Abase + ki * GM_BK, Bbase + ki * GM_BK, tid);
        }

        const int s = it % GM_NST;
        As0 = gsm + (size_t)s * GM_STAGE_FLOATS;
        Bs0 = As0 + 128 * GM_LDS;

#pragma unroll
        for (int k0 = 0; k0 < GM_BK; k0 += 8) {
            uint32_t af[2][4];
#pragma unroll
            for (int mt = 0; mt < 2; mt++) {
                int r = wm * 32 + mt * 16 + gid;
                af[mt][0] = __float_as_uint(As0[r * GM_LDS + k0 + tig]);
                af[mt][1] = __float_as_uint(As0[(r + 8) * GM_LDS + k0 + tig]);
                af[mt][2] = __float_as_uint(As0[r * GM_LDS + k0 + tig + 4]);
                af[mt][3] = __float_as_uint(As0[(r + 8) * GM_LDS + k0 + tig + 4]);
            }
#pragma unroll
            for (int nt = 0; nt < 8; nt++) {
                int rn = wn * 64 + nt * 8 + gid;
                uint32_t b0 = __float_as_uint(Bs0[rn * GM_LDS + k0 + tig]);
                uint32_t b1 = __float_as_uint(Bs0[rn * GM_LDS + k0 + tig + 4]);
#pragma unroll
                for (int mt = 0; mt < 2; mt++)
                    mma_tf32(acc[mt][nt][0], acc[mt][nt][1], acc[mt][nt][2], acc[mt][nt][3],
                             af[mt][0], af[mt][1], af[mt][2], af[mt][3], b0, b1);
            }
        }
    }

    // epilogue: direct stores
#pragma unroll
    for (int mt = 0; mt < 2; mt++) {
        int r0 = bm + wm * 32 + mt * 16 + gid;
#pragma unroll
        for (int nt = 0; nt < 8; nt++) {
            int c = bn + wn * 64 + nt * 8 + tig * 2;
            float2 v0 = make_float2(acc[mt][nt][0], acc[mt][nt][1]);
            float2 v1 = make_float2(acc[mt][nt][2], acc[mt][nt][3]);
            *(float2*)(C + (size_t)r0 * N + c)       = v0;
            *(float2*)(C + (size_t)(r0 + 8) * N + c) = v1;
        }
    }
}

// ---------------- fused RMSNorm + RoPE ----------------
__global__ void __launch_bounds__(128) rmsrope_kernel(
    float* __restrict__ buf, const float* __restrict__ w,
    const float* __restrict__ cosb, const float* __restrict__ sinb, int nheads)
{
    const int bh  = blockIdx.x;
    const int row = bh / nheads;
    const int h   = bh - row * nheads;
    const int s   = row & (S_ - 1);
    const int d   = threadIdx.x;

    float* p = buf + ((size_t)row * nheads + h) * DH;
    float v = p[d];

    float ss = v * v;
#pragma unroll
    for (int o = 16; o > 0; o >>= 1) ss += __shfl_xor_sync(0xffffffffu, ss, o);
    __shared__ float sh[4];
    if ((d & 31) == 0) sh[d >> 5] = ss;
    __syncthreads();
    float tot = sh[0] + sh[1] + sh[2] + sh[3];
    float inv = rsqrtf(tot * (1.0f / DH) + EPS);

    int pd = d ^ 64;
    float pv  = p[pd];
    float nv  = w[d]  * v  * inv;
    float npv = w[pd] * pv * inv;
    float c  = cosb[(size_t)s * DH + d];
    float sn = sinb[(size_t)s * DH + d];
    float out = nv * c + ((d < 64) ? -npv : npv) * sn;
    __syncthreads();
    p[d] = out;
}

// ---------------- flash attention, fp32, causal ----------------
#define KS_STRIDE 129
#define FLASH_SMEM_FLOATS (128*64 + 64*KS_STRIDE + 64*128 + 64*64)

__global__ void __launch_bounds__(128) flash_kernel(
    const float* __restrict__ Qg, const float* __restrict__ Kg,
    const float* __restrict__ Vg, float* __restrict__ Og)
{
    extern __shared__ float smem[];
    float* Qs = smem;
    float* Ks = Qs + 128 * 64;
    float* Vs = Ks + 64 * KS_STRIDE;
    float* Ps = Vs + 64 * 128;

    const int qt  = blockIdx.x;
    const int h   = blockIdx.y;
    const int b   = blockIdx.z;
    const int kvh = h / (NH / NKV);
    const int tid = threadIdx.x;
    const int rg  = tid >> 4;
    const int cg  = tid & 15;
    const int r0  = rg * 8;
    const int c0  = cg * 4;

    const float scale = 0.08838834764831845f;

    {
        const size_t qbase = ((size_t)(b * S_ + qt * 64)) * (NH * DH) + (size_t)h * DH;
#pragma unroll
        for (int i = tid; i < 64 * 32; i += 128) {
            int m = i >> 5, d4 = i & 31;
            float4 v = *(const float4*)(Qg + qbase + (size_t)m * (NH * DH) + d4 * 4);
            Qs[(d4 * 4 + 0) * 64 + m] = v.x * scale;
            Qs[(d4 * 4 + 1) * 64 + m] = v.y * scale;
            Qs[(d4 * 4 + 2) * 64 + m] = v.z * scale;
            Qs[(d4 * 4 + 3) * 64 + m] = v.w * scale;
        }
    }

    float acc[8][8];
#pragma unroll
    for (int i = 0; i < 8; i++)
#pragma unroll
        for (int j = 0; j < 8; j++) acc[i][j] = 0.f;
    float mrow[8], lrow[8];
#pragma unroll
    for (int i = 0; i < 8; i++) { mrow[i] = -1e30f; lrow[i] = 0.f; }

    for (int kt = 0; kt <= qt; kt++) {
        const size_t kbase = ((size_t)(b * S_ + kt * 64)) * (NKV * DH) + (size_t)kvh * DH;
#pragma unroll
        for (int i = tid; i < 64 * 32; i += 128) {
            int n = i >> 5, d4 = i & 31;
            float4 kv = *(const float4*)(Kg + kbase + (size_t)n * (NKV * DH) + d4 * 4);
            Ks[n * KS_STRIDE + d4 * 4 + 0] = kv.x;
            Ks[n * KS_STRIDE + d4 * 4 + 1] = kv.y;
            Ks[n * KS_STRIDE + d4 * 4 + 2] = kv.z;
            Ks[n * KS_STRIDE + d4 * 4 + 3] = kv.w;
            float4 vv = *(const float4*)(Vg + kbase + (size_t)n * (NKV * DH) + d4 * 4);
            *(float4*)(Vs + n * 128 + d4 * 4) = vv;
        }
        __syncthreads();

        float s[8][4];
#pragma unroll
        for (int i = 0; i < 8; i++)
#pragma unroll
            for (int j = 0; j < 4; j++) s[i][j] = 0.f;

#pragma unroll 4
        for (int d = 0; d < 128; d++) {
            float4 qa = *(const float4*)(Qs + d * 64 + r0);
            float4 qb = *(const float4*)(Qs + d * 64 + r0 + 4);
            float qv[8] = {qa.x, qa.y, qa.z, qa.w, qb.x, qb.y, qb.z, qb.w};
            float kv[4];
#pragma unroll
            for (int j = 0; j < 4; j++) kv[j] = Ks[(c0 + j) * KS_STRIDE + d];
#pragma unroll
            for (int i = 0; i < 8; i++)
#pragma unroll
                for (int j = 0; j < 4; j++)
                    s[i][j] += qv[i] * kv[j];
        }

        if (kt == qt) {
#pragma unroll
            for (int i = 0; i < 8; i++)
#pragma unroll
                for (int j = 0; j < 4; j++)
                    if (c0 + j > r0 + i) s[i][j] = -1e30f;
        }

#pragma unroll
        for (int i = 0; i < 8; i++) {
            float mx = s[i][0];
            mx = fmaxf(mx, s[i][1]); mx = fmaxf(mx, s[i][2]); mx = fmaxf(mx, s[i][3]);
#pragma unroll
            for (int o = 8; o > 0; o >>= 1)
                mx = fmaxf(mx, __shfl_xor_sync(0xffffffffu, mx, o));
            float mnew = fmaxf(mrow[i], mx);
            float f = __expf(mrow[i] - mnew);
            mrow[i] = mnew;
            float ls = 0.f;
#pragma unroll
            for (int j = 0; j < 4; j++) {
                float pj = __expf(s[i][j] - mnew);
                s[i][j] = pj;
                ls += pj;
            }
#pragma unroll
            for (int o = 8; o > 0; o >>= 1)
                ls += __shfl_xor_sync(0xffffffffu, ls, o);
            lrow[i] = lrow[i] * f + ls;
#pragma unroll
            for (int j = 0; j < 8; j++) acc[i][j] *= f;
#pragma unroll
            for (int j = 0; j < 4; j++)
                Ps[(r0 + i) * 64 + c0 + j] = s[i][j];
        }
        __syncthreads();

#pragma unroll 2
        for (int n = 0; n < 64; n++) {
            float4 va = *(const float4*)(Vs + n * 128 + cg * 8);
            float4 vb = *(const float4*)(Vs + n * 128 + cg * 8 + 4);
            float vv[8] = {va.x, va.y, va.z, va.w, vb.x, vb.y, vb.z, vb.w};
#pragma unroll
            for (int i = 0; i < 8; i++) {
                float p = Ps[(r0 + i) * 64 + n];
#pragma unroll
                for (int j = 0; j < 8; j++)
                    acc[i][j] += p * vv[j];
            }
        }
        __syncthreads();
    }

    const size_t obase = ((size_t)(b * S_ + qt * 64)) * (NH * DH) + (size_t)h * DH;
#pragma unroll
    for (int i = 0; i < 8; i++) {
        float invl = 1.0f / lrow[i];
        float4 o0 = make_float4(acc[i][0] * invl, acc[i][1] * invl,
                                acc[i][2] * invl, acc[i][3] * invl);
        float4 o1 = make_float4(acc[i][4] * invl, acc[i][5] * invl,
                                acc[i][6] * invl, acc[i][7] * invl);
        size_t off = obase + (size_t)(r0 + i) * (NH * DH) + cg * 8;
        *(float4*)(Og + off)     = o0;
        *(float4*)(Og + off + 4) = o1;
    }
}

// ---------------- launch ----------------
extern "C" void kernel_launch(void* const* d_in, const int* in_sizes, int n_in,
                              void* d_out, int out_size)
{
    const float* X    = (const float*)d_in[0];
    // d_in[1] = attention_mask: exact causal mask, applied analytically — unused
    const float* cosp = (const float*)d_in[2];
    const float* sinp = (const float*)d_in[3];
    const float* Wq   = (const float*)d_in[4];
    const float* Wk   = (const float*)d_in[5];
    const float* Wv   = (const float*)d_in[6];
    const float* Wo   = (const float*)d_in[7];
    const float* qnw  = (const float*)d_in[8];
    const float* knw  = (const float*)d_in[9];
    float* out = (float*)d_out;

    float *Xr, *Q, *K, *V, *O, *WqT, *WkT, *WvT, *WoT;
    cudaGetSymbolAddress((void**)&Xr,  g_X);
    cudaGetSymbolAddress((void**)&Q,   g_Q);
    cudaGetSymbolAddress((void**)&K,   g_K);
    cudaGetSymbolAddress((void**)&V,   g_V);
    cudaGetSymbolAddress((void**)&O,   g_O);
    cudaGetSymbolAddress((void**)&WqT, g_WqT);
    cudaGetSymbolAddress((void**)&WkT, g_WkT);
    cudaGetSymbolAddress((void**)&WvT, g_WvT);
    cudaGetSymbolAddress((void**)&WoT, g_WoT);

    cudaFuncSetAttribute(gemm_tf32mma_kernel, cudaFuncAttributeMaxDynamicSharedMemorySize,
                         GM_SMEM_BYTES);
    static const size_t flash_smem = (size_t)FLASH_SMEM_FLOATS * sizeof(float);
    cudaFuncSetAttribute(flash_kernel, cudaFuncAttributeMaxDynamicSharedMemorySize,
                         (int)flash_smem);

    // tf32-round X; transpose+round weights
    tf32_round_kernel<<<2048, 256>>>(Xr, X, (size_t)MROWS * HID / 4);
    transpose_tf32_kernel<<<dim3((NH * DH) / 32, HID / 32), dim3(32, 8)>>>(WqT, Wq, HID, NH * DH);
    transpose_tf32_kernel<<<dim3((NKV * DH) / 32, HID / 32), dim3(32, 8)>>>(WkT, Wk, HID, NKV * DH);
    transpose_tf32_kernel<<<dim3((NKV * DH) / 32, HID / 32), dim3(32, 8)>>>(WvT, Wv, HID, NKV * DH);
    transpose_tf32_kernel<<<dim3(HID / 32, (NH * DH) / 32), dim3(32, 8)>>>(WoT, Wo, NH * DH, HID);

    // QKV projections (tensor cores via mma.sync tf32)
    gemm_tf32mma_kernel<<<dim3(NH * DH / GM_BN, MROWS / GM_BM), 256, GM_SMEM_BYTES>>>(
        Xr, WqT, Q, MROWS, NH * DH);
    gemm_tf32mma_kernel<<<dim3(NKV * DH / GM_BN, MROWS / GM_BM), 256, GM_SMEM_BYTES>>>(
        Xr, WkT, K, MROWS, NKV * DH);
    gemm_tf32mma_kernel<<<dim3(NKV * DH / GM_BN, MROWS / GM_BM), 256, GM_SMEM_BYTES>>>(
        Xr, WvT, V, MROWS, NKV * DH);

    // RMSNorm + RoPE
    rmsrope_kernel<<<MROWS * NH, 128>>>(Q, qnw, cosp, sinp, NH);
    rmsrope_kernel<<<MROWS * NKV, 128>>>(K, knw, cosp, sinp, NKV);

    // Flash attention (fp32)
    flash_kernel<<<dim3(S_ / 64, NH, B_), 128, flash_smem>>>(Q, K, V, O);

    // Round attention output, then O-projection (tensor cores)
    tf32_round_kernel<<<2048, 256>>>(O, O, (size_t)MROWS * NH * DH / 4);
    gemm_tf32mma_kernel<<<dim3(HID / GM_BN, MROWS / GM_BM), 256, GM_SMEM_BYTES>>>(
        O, WoT, out, MROWS, HID);
}

// round 6
// speedup vs baseline: 2.9772x; 1.6933x over previous
#include <cuda_runtime.h>
#include <cuda_bf16.h>
#include <math.h>
#include <stdint.h>

// Problem constants
#define B_  2
#define S_  2048
#define HID 2048
#define NH  16
#define NKV 4
#define DH  128
#define MROWS (B_ * S_)        // 4096
#define EPS 1e-6f

// ---------------- scratch ----------------
__device__ float g_X [(size_t)MROWS * HID];      // tf32-rounded hidden states
__device__ float g_Q [(size_t)MROWS * NH * DH];
__device__ float g_K [(size_t)MROWS * NKV * DH];
__device__ float g_V [(size_t)MROWS * NKV * DH];
__device__ float g_O [(size_t)MROWS * NH * DH];
__device__ float g_WqT[(size_t)HID * NH * DH];   // [N][K] transposed, tf32-rounded
__device__ float g_WkT[(size_t)HID * NKV * DH];
__device__ float g_WvT[(size_t)HID * NKV * DH];
__device__ float g_WoT[(size_t)NH * DH * HID];

// ---------------- helpers ----------------
__device__ __forceinline__ uint32_t smem_u32(const void* p) {
    uint32_t a;
    asm("{ .reg .u64 t; cvta.to.shared.u64 t, %1; cvt.u32.u64 %0, t; }" : "=r"(a) : "l"(p));
    return a;
}
__device__ __forceinline__ float tf32r(float x) {
    uint32_t r;
    asm("cvt.rna.tf32.f32 %0, %1;" : "=r"(r) : "f"(x));
    return __uint_as_float(r);
}
#define CP_ASYNC16(sdst, gsrc) \
    asm volatile("cp.async.cg.shared.global [%0], [%1], 16;" :: "r"(sdst), "l"(gsrc))
#define CP_COMMIT() asm volatile("cp.async.commit_group;" ::: "memory")
#define CP_WAIT(n)  asm volatile("cp.async.wait_group %0;" :: "n"(n) : "memory")

__device__ __forceinline__ void mma_tf32(float& c0, float& c1, float& c2, float& c3,
                                         uint32_t a0, uint32_t a1, uint32_t a2, uint32_t a3,
                                         uint32_t b0, uint32_t b1) {
    asm volatile(
        "mma.sync.aligned.m16n8k8.row.col.f32.tf32.tf32.f32 "
        "{%0,%1,%2,%3}, {%4,%5,%6,%7}, {%8,%9}, {%0,%1,%2,%3};"
        : "+f"(c0), "+f"(c1), "+f"(c2), "+f"(c3)
        : "r"(a0), "r"(a1), "r"(a2), "r"(a3), "r"(b0), "r"(b1));
}

// ---------------- tf32 rounding (elementwise, in/out may alias) ----------------
__global__ void __launch_bounds__(256) tf32_round_kernel(float* __restrict__ dst,
                                                         const float* __restrict__ src,
                                                         size_t n4) {
    for (size_t i = blockIdx.x * blockDim.x + threadIdx.x; i < n4;
         i += (size_t)gridDim.x * blockDim.x) {
        float4 v = ((const float4*)src)[i];
        v.x = tf32r(v.x); v.y = tf32r(v.y); v.z = tf32r(v.z); v.w = tf32r(v.w);
        ((float4*)dst)[i] = v;
    }
}

// ---------------- transpose + tf32 round: dst[C][R] = tf32(src[R][C]) ----------------
__global__ void __launch_bounds__(256) transpose_tf32_kernel(float* __restrict__ dst,
                                                             const float* __restrict__ src,
                                                             int R, int C) {
    __shared__ float t[32][33];
    int bx = blockIdx.x * 32;     // col tile
    int by = blockIdx.y * 32;     // row tile
    int tx = threadIdx.x, ty = threadIdx.y;     // 32 x 8
#pragma unroll
    for (int i = 0; i < 4; i++)
        t[ty + i * 8][tx] = src[(size_t)(by + ty + i * 8) * C + bx + tx];
    __syncthreads();
#pragma unroll
    for (int i = 0; i < 4; i++)
        dst[(size_t)(bx + ty + i * 8) * R + by + tx] = tf32r(t[tx][ty + i * 8]);
}

// ---------------- tf32 mma.sync GEMM (unchanged from R5) ----------------
#define GK      2048
#define GM_BM   128
#define GM_BN   128
#define GM_BK   16
#define GM_LDS  20
#define GM_NST  3
#define GM_NIT  (GK / GM_BK)
#define GM_STAGE_FLOATS (2 * 128 * GM_LDS)
#define GM_SMEM_BYTES (GM_NST * GM_STAGE_FLOATS * 4)   // 61440

__device__ __forceinline__ void gm_load_stage(uint32_t sA, uint32_t sB,
                                              const float* __restrict__ Atile,
                                              const float* __restrict__ Btile,
                                              int tid) {
#pragma unroll
    for (int i = 0; i < 2; i++) {
        int idx = i * 256 + tid;
        int r = idx >> 2, c = idx & 3;
        CP_ASYNC16(sA + (uint32_t)(r * (GM_LDS * 4) + c * 16),
                   Atile + (size_t)r * GK + c * 4);
    }
#pragma unroll
    for (int i = 0; i < 2; i++) {
        int idx = i * 256 + tid;
        int r = idx >> 2, c = idx & 3;
        CP_ASYNC16(sB + (uint32_t)(r * (GM_LDS * 4) + c * 16),
                   Btile + (size_t)r * GK + c * 4);
    }
    CP_COMMIT();
}

__global__ void __launch_bounds__(256, 1) gemm_tf32mma_kernel(
    const float* __restrict__ A, const float* __restrict__ Bt,
    float* __restrict__ C, int M, int N)
{
    extern __shared__ float gsm[];
    const uint32_t sbase = smem_u32(gsm);
    const int tid = threadIdx.x;
    const int wid = tid >> 5, lid = tid & 31;
    const int wm = wid >> 1;
    const int wn = wid & 1;
    const int gid = lid >> 2;
    const int tig = lid & 3;
    const int bm = blockIdx.y * GM_BM;
    const int bn = blockIdx.x * GM_BN;

    float acc[2][8][4];
#pragma unroll
    for (int mt = 0; mt < 2; mt++)
#pragma unroll
        for (int nt = 0; nt < 8; nt++)
#pragma unroll
            for (int q = 0; q < 4; q++) acc[mt][nt][q] = 0.f;

    const float* Abase = A + (size_t)bm * GK;
    const float* Bbase = Bt + (size_t)bn * GK;

    uint32_t stA[GM_NST], stB[GM_NST];
#pragma unroll
    for (int s = 0; s < GM_NST; s++) {
        stA[s] = sbase + (uint32_t)(s * GM_STAGE_FLOATS * 4);
        stB[s] = stA[s] + 128u * GM_LDS * 4u;
    }

    gm_load_stage(stA[0], stB[0], Abase, Bbase, tid);
    gm_load_stage(stA[1], stB[1], Abase + GM_BK, Bbase + GM_BK, tid);

    const float* As0;
    const float* Bs0;

    for (int it = 0; it < GM_NIT; it++) {
        CP_WAIT(1);
        __syncthreads();

        const int ki = it + 2;
        if (ki < GM_NIT) {
            const int b = ki % GM_NST;
            gm_load_stage(stA[b], stB[b], Abase + ki * GM_BK, Bbase + ki * GM_BK, tid);
        }

        const int s = it % GM_NST;
        As0 = gsm + (size_t)s * GM_STAGE_FLOATS;
        Bs0 = As0 + 128 * GM_LDS;

#pragma unroll
        for (int k0 = 0; k0 < GM_BK; k0 += 8) {
            uint32_t af[2][4];
#pragma unroll
            for (int mt = 0; mt < 2; mt++) {
                int r = wm * 32 + mt * 16 + gid;
                af[mt][0] = __float_as_uint(As0[r * GM_LDS + k0 + tig]);
                af[mt][1] = __float_as_uint(As0[(r + 8) * GM_LDS + k0 + tig]);
                af[mt][2] = __float_as_uint(As0[r * GM_LDS + k0 + tig + 4]);
                af[mt][3] = __float_as_uint(As0[(r + 8) * GM_LDS + k0 + tig + 4]);
            }
#pragma unroll
            for (int nt = 0; nt < 8; nt++) {
                int rn = wn * 64 + nt * 8 + gid;
                uint32_t b0 = __float_as_uint(Bs0[rn * GM_LDS + k0 + tig]);
                uint32_t b1 = __float_as_uint(Bs0[rn * GM_LDS + k0 + tig + 4]);
#pragma unroll
                for (int mt = 0; mt < 2; mt++)
                    mma_tf32(acc[mt][nt][0], acc[mt][nt][1], acc[mt][nt][2], acc[mt][nt][3],
                             af[mt][0], af[mt][1], af[mt][2], af[mt][3], b0, b1);
            }
        }
    }

#pragma unroll
    for (int mt = 0; mt < 2; mt++) {
        int r0 = bm + wm * 32 + mt * 16 + gid;
#pragma unroll
        for (int nt = 0; nt < 8; nt++) {
            int c = bn + wn * 64 + nt * 8 + tig * 2;
            float2 v0 = make_float2(acc[mt][nt][0], acc[mt][nt][1]);
            float2 v1 = make_float2(acc[mt][nt][2], acc[mt][nt][3]);
            *(float2*)(C + (size_t)r0 * N + c)       = v0;
            *(float2*)(C + (size_t)(r0 + 8) * N + c) = v1;
        }
    }
}

// ---------------- fused RMSNorm + RoPE (now writes tf32-rounded) ----------------
__global__ void __launch_bounds__(128) rmsrope_kernel(
    float* __restrict__ buf, const float* __restrict__ w,
    const float* __restrict__ cosb, const float* __restrict__ sinb, int nheads)
{
    const int bh  = blockIdx.x;
    const int row = bh / nheads;
    const int h   = bh - row * nheads;
    const int s   = row & (S_ - 1);
    const int d   = threadIdx.x;

    float* p = buf + ((size_t)row * nheads + h) * DH;
    float v = p[d];

    float ss = v * v;
#pragma unroll
    for (int o = 16; o > 0; o >>= 1) ss += __shfl_xor_sync(0xffffffffu, ss, o);
    __shared__ float sh[4];
    if ((d & 31) == 0) sh[d >> 5] = ss;
    __syncthreads();
    float tot = sh[0] + sh[1] + sh[2] + sh[3];
    float inv = rsqrtf(tot * (1.0f / DH) + EPS);

    int pd = d ^ 64;
    float pv  = p[pd];
    float nv  = w[d]  * v  * inv;
    float npv = w[pd] * pv * inv;
    float c  = cosb[(size_t)s * DH + d];
    float sn = sinb[(size_t)s * DH + d];
    float out = nv * c + ((d < 64) ? -npv : npv) * sn;
    __syncthreads();
    p[d] = tf32r(out);
}

// ---------------- tensor-core flash attention (tf32 mma), causal ----------------
// BM=128 (q rows), BN=64 (kv cols), 256 threads = 8 warps x 16 rows.
// Qs[m][FPAD] row-major; Ks[n][FPAD] (K-major = .col B operand);
// Vs[d][VPAD] (transposed, B operand for PV); Ps[m][VPAD] (P fragment relayout).
#define FPAD 132
#define VPAD 68
#define FT_SMEM_FLOATS (128*FPAD + 64*FPAD + 128*VPAD + 128*VPAD)   // 42752
#define FT_SMEM_BYTES  (FT_SMEM_FLOATS * 4)                          // 171008

__global__ void __launch_bounds__(256, 1) flash_tc_kernel(
    const float* __restrict__ Qg, const float* __restrict__ Kg,
    const float* __restrict__ Vg, float* __restrict__ Og)
{
    extern __shared__ float fsm[];
    float* Qs = fsm;                    // [128][FPAD]
    float* Ks = Qs + 128 * FPAD;        // [64][FPAD]
    float* Vs = Ks + 64 * FPAD;         // [128][VPAD]  (d-major)
    float* Ps = Vs + 128 * VPAD;        // [128][VPAD]

    const int qt  = (int)gridDim.x - 1 - (int)blockIdx.x;   // long blocks first
    const int h   = blockIdx.y;
    const int b   = blockIdx.z;
    const int kvh = h >> 2;             // NH/NKV = 4
    const int tid = threadIdx.x;
    const int wid = tid >> 5, lid = tid & 31;
    const int gid = lid >> 2, tig = lid & 3;
    const int wrow = wid * 16;          // warp's 16 rows in the 128-row tile
    const float scale = 0.08838834764831845f;   // 1/sqrt(128)

    // Load Q tile (straight layout)
    const size_t qbase = ((size_t)(b * S_ + qt * 128)) * (NH * DH) + (size_t)h * DH;
#pragma unroll
    for (int i = tid; i < 128 * 32; i += 256) {
        int m = i >> 5, d4 = i & 31;
        *(float4*)(Qs + m * FPAD + d4 * 4) =
            *(const float4*)(Qg + qbase + (size_t)m * (NH * DH) + d4 * 4);
    }

    float oacc[16][4];
#pragma unroll
    for (int db = 0; db < 16; db++)
#pragma unroll
        for (int q = 0; q < 4; q++) oacc[db][q] = 0.f;
    float m1 = -1e30f, m2 = -1e30f, l1 = 0.f, l2 = 0.f;

    const int r1loc = wrow + gid;       // local row of c0/c1
    const int r2loc = r1loc + 8;        // local row of c2/c3
    const int r1g = qt * 128 + r1loc;
    const int r2g = r1g + 8;

    const int ntiles = 2 * qt + 2;
    for (int j = 0; j < ntiles; j++) {
        const size_t kb = ((size_t)(b * S_ + j * 64)) * (NKV * DH) + (size_t)kvh * DH;
        __syncthreads();                // prior iter's Ks/Vs reads complete
        // K tile [n][d]
#pragma unroll
        for (int i = tid; i < 64 * 32; i += 256) {
            int n = i >> 5, d4 = i & 31;
            *(float4*)(Ks + n * FPAD + d4 * 4) =
                *(const float4*)(Kg + kb + (size_t)n * (NKV * DH) + d4 * 4);
        }
        // V tile transposed -> Vs[d][n]
#pragma unroll
        for (int i = tid; i < 64 * 32; i += 256) {
            int n = i & 63, d4 = i >> 6;
            float4 v = *(const float4*)(Vg + kb + (size_t)n * (NKV * DH) + d4 * 4);
            Vs[(d4 * 4 + 0) * VPAD + n] = v.x;
            Vs[(d4 * 4 + 1) * VPAD + n] = v.y;
            Vs[(d4 * 4 + 2) * VPAD + n] = v.z;
            Vs[(d4 * 4 + 3) * VPAD + n] = v.w;
        }
        __syncthreads();

        // S = Q @ K^T  (16 k-steps of 8)
        float sacc[8][4];
#pragma unroll
        for (int nb = 0; nb < 8; nb++)
#pragma unroll
            for (int q = 0; q < 4; q++) sacc[nb][q] = 0.f;

#pragma unroll
        for (int ks = 0; ks < 16; ks++) {
            int k0 = ks * 8;
            uint32_t a0 = __float_as_uint(Qs[r1loc * FPAD + k0 + tig]);
            uint32_t a1 = __float_as_uint(Qs[r2loc * FPAD + k0 + tig]);
            uint32_t a2 = __float_as_uint(Qs[r1loc * FPAD + k0 + tig + 4]);
            uint32_t a3 = __float_as_uint(Qs[r2loc * FPAD + k0 + tig + 4]);
#pragma unroll
            for (int nb = 0; nb < 8; nb++) {
                uint32_t b0 = __float_as_uint(Ks[(nb * 8 + gid) * FPAD + k0 + tig]);
                uint32_t b1 = __float_as_uint(Ks[(nb * 8 + gid) * FPAD + k0 + tig + 4]);
                mma_tf32(sacc[nb][0], sacc[nb][1], sacc[nb][2], sacc[nb][3],
                         a0, a1, a2, a3, b0, b1);
            }
        }

        // scale (fp32) + causal mask (only last two tiles can cross the diagonal)
        const bool masked = (j >= 2 * qt);
#pragma unroll
        for (int nb = 0; nb < 8; nb++) {
            int c0g = j * 64 + nb * 8 + tig * 2;
            int c1g = c0g + 1;
            sacc[nb][0] = (masked && c0g > r1g) ? -1e30f : sacc[nb][0] * scale;
            sacc[nb][1] = (masked && c1g > r1g) ? -1e30f : sacc[nb][1] * scale;
            sacc[nb][2] = (masked && c0g > r2g) ? -1e30f : sacc[nb][2] * scale;
            sacc[nb][3] = (masked && c1g > r2g) ? -1e30f : sacc[nb][3] * scale;
        }

        // row max (thread-local then quad shfl)
        float mx1 = -1e30f, mx2 = -1e30f;
#pragma unroll
        for (int nb = 0; nb < 8; nb++) {
            mx1 = fmaxf(mx1, fmaxf(sacc[nb][0], sacc[nb][1]));
            mx2 = fmaxf(mx2, fmaxf(sacc[nb][2], sacc[nb][3]));
        }
        mx1 = fmaxf(mx1, __shfl_xor_sync(0xffffffffu, mx1, 1));
        mx1 = fmaxf(mx1, __shfl_xor_sync(0xffffffffu, mx1, 2));
        mx2 = fmaxf(mx2, __shfl_xor_sync(0xffffffffu, mx2, 1));
        mx2 = fmaxf(mx2, __shfl_xor_sync(0xffffffffu, mx2, 2));

        float mn1 = fmaxf(m1, mx1), mn2 = fmaxf(m2, mx2);
        float f1 = __expf(m1 - mn1), f2 = __expf(m2 - mn2);
        m1 = mn1; m2 = mn2;

        // probs + row sums; tf32-round before Ps store
        float ls1 = 0.f, ls2 = 0.f;
#pragma unroll
        for (int nb = 0; nb < 8; nb++) {
            float p0 = __expf(sacc[nb][0] - mn1);
            float p1 = __expf(sacc[nb][1] - mn1);
            float p2 = __expf(sacc[nb][2] - mn2);
            float p3 = __expf(sacc[nb][3] - mn2);
            ls1 += p0 + p1;
            ls2 += p2 + p3;
            int c0 = nb * 8 + tig * 2;
            *(float2*)(Ps + r1loc * VPAD + c0) = make_float2(tf32r(p0), tf32r(p1));
            *(float2*)(Ps + r2loc * VPAD + c0) = make_float2(tf32r(p2), tf32r(p3));
        }
        ls1 += __shfl_xor_sync(0xffffffffu, ls1, 1);
        ls1 += __shfl_xor_sync(0xffffffffu, ls1, 2);
        ls2 += __shfl_xor_sync(0xffffffffu, ls2, 1);
        ls2 += __shfl_xor_sync(0xffffffffu, ls2, 2);
        l1 = l1 * f1 + ls1;
        l2 = l2 * f2 + ls2;

        // rescale O accumulators
#pragma unroll
        for (int db = 0; db < 16; db++) {
            oacc[db][0] *= f1; oacc[db][1] *= f1;
            oacc[db][2] *= f2; oacc[db][3] *= f2;
        }
        __syncwarp();

        // O += P @ V  (8 k-steps over kv; Vs is [d][n], b = Vs[dcol][k])
#pragma unroll
        for (int ks = 0; ks < 8; ks++) {
            int k0 = ks * 8;
            uint32_t a0 = __float_as_uint(Ps[r1loc * VPAD + k0 + tig]);
            uint32_t a1 = __float_as_uint(Ps[r2loc * VPAD + k0 + tig]);
            uint32_t a2 = __float_as_uint(Ps[r1loc * VPAD + k0 + tig + 4]);
            uint32_t a3 = __float_as_uint(Ps[r2loc * VPAD + k0 + tig + 4]);
#pragma unroll
            for (int db = 0; db < 16; db++) {
                uint32_t b0 = __float_as_uint(Vs[(db * 8 + gid) * VPAD + k0 + tig]);
                uint32_t b1 = __float_as_uint(Vs[(db * 8 + gid) * VPAD + k0 + tig + 4]);
                mma_tf32(oacc[db][0], oacc[db][1], oacc[db][2], oacc[db][3],
                         a0, a1, a2, a3, b0, b1);
            }
        }
    }

    // epilogue: normalize, tf32-round (input to O-proj GEMM), write
    const float inv1 = 1.0f / l1, inv2 = 1.0f / l2;
    const size_t obase = ((size_t)(b * S_ + qt * 128)) * (NH * DH) + (size_t)h * DH;
#pragma unroll
    for (int db = 0; db < 16; db++) {
        int c = db * 8 + tig * 2;
        *(float2*)(Og + obase + (size_t)r1loc * (NH * DH) + c) =
            make_float2(tf32r(oacc[db][0] * inv1), tf32r(oacc[db][1] * inv1));
        *(float2*)(Og + obase + (size_t)r2loc * (NH * DH) + c) =
            make_float2(tf32r(oacc[db][2] * inv2), tf32r(oacc[db][3] * inv2));
    }
}

// ---------------- launch ----------------
extern "C" void kernel_launch(void* const* d_in, const int* in_sizes, int n_in,
                              void* d_out, int out_size)
{
    const float* X    = (const float*)d_in[0];
    // d_in[1] = attention_mask: exact causal mask, applied analytically — unused
    const float* cosp = (const float*)d_in[2];
    const float* sinp = (const float*)d_in[3];
    const float* Wq   = (const float*)d_in[4];
    const float* Wk   = (const float*)d_in[5];
    const float* Wv   = (const float*)d_in[6];
    const float* Wo   = (const float*)d_in[7];
    const float* qnw  = (const float*)d_in[8];
    const float* knw  = (const float*)d_in[9];
    float* out = (float*)d_out;

    float *Xr, *Q, *K, *V, *O, *WqT, *WkT, *WvT, *WoT;
    cudaGetSymbolAddress((void**)&Xr,  g_X);
    cudaGetSymbolAddress((void**)&Q,   g_Q);
    cudaGetSymbolAddress((void**)&K,   g_K);
    cudaGetSymbolAddress((void**)&V,   g_V);
    cudaGetSymbolAddress((void**)&O,   g_O);
    cudaGetSymbolAddress((void**)&WqT, g_WqT);
    cudaGetSymbolAddress((void**)&WkT, g_WkT);
    cudaGetSymbolAddress((void**)&WvT, g_WvT);
    cudaGetSymbolAddress((void**)&WoT, g_WoT);

    cudaFuncSetAttribute(gemm_tf32mma_kernel, cudaFuncAttributeMaxDynamicSharedMemorySize,
                         GM_SMEM_BYTES);
    cudaFuncSetAttribute(flash_tc_kernel, cudaFuncAttributeMaxDynamicSharedMemorySize,
                         FT_SMEM_BYTES);

    // tf32-round X; transpose+round weights
    tf32_round_kernel<<<2048, 256>>>(Xr, X, (size_t)MROWS * HID / 4);
    transpose_tf32_kernel<<<dim3((NH * DH) / 32, HID / 32), dim3(32, 8)>>>(WqT, Wq, HID, NH * DH);
    transpose_tf32_kernel<<<dim3((NKV * DH) / 32, HID / 32), dim3(32, 8)>>>(WkT, Wk, HID, NKV * DH);
    transpose_tf32_kernel<<<dim3((NKV * DH) / 32, HID / 32), dim3(32, 8)>>>(WvT, Wv, HID, NKV * DH);
    transpose_tf32_kernel<<<dim3(HID / 32, (NH * DH) / 32), dim3(32, 8)>>>(WoT, Wo, NH * DH, HID);

    // QKV projections (tensor cores via mma.sync tf32)
    gemm_tf32mma_kernel<<<dim3(NH * DH / GM_BN, MROWS / GM_BM), 256, GM_SMEM_BYTES>>>(
        Xr, WqT, Q, MROWS, NH * DH);
    gemm_tf32mma_kernel<<<dim3(NKV * DH / GM_BN, MROWS / GM_BM), 256, GM_SMEM_BYTES>>>(
        Xr, WkT, K, MROWS, NKV * DH);
    gemm_tf32mma_kernel<<<dim3(NKV * DH / GM_BN, MROWS / GM_BM), 256, GM_SMEM_BYTES>>>(
        Xr, WvT, V, MROWS, NKV * DH);

    // RMSNorm + RoPE (outputs tf32-rounded); round V for the PV MMA
    rmsrope_kernel<<<MROWS * NH, 128>>>(Q, qnw, cosp, sinp, NH);
    rmsrope_kernel<<<MROWS * NKV, 128>>>(K, knw, cosp, sinp, NKV);
    tf32_round_kernel<<<1024, 256>>>(V, V, (size_t)MROWS * NKV * DH / 4);

    // Flash attention (tensor cores)
    flash_tc_kernel<<<dim3(S_ / 128, NH, B_), 256, FT_SMEM_BYTES>>>(Q, K, V, O);

    // O-projection (tensor cores); O already tf32-rounded by flash epilogue
    gemm_tf32mma_kernel<<<dim3(HID / GM_BN, MROWS / GM_BM), 256, GM_SMEM_BYTES>>>(
        O, WoT, out, MROWS, HID);
}

// round 8
// speedup vs baseline: 3.2734x; 1.0995x over previous
#include <cuda_runtime.h>
#include <cuda_bf16.h>
#include <math.h>
#include <stdint.h>

// Problem constants
#define B_  2
#define S_  2048
#define HID 2048
#define NH  16
#define NKV 4
#define DH  128
#define MROWS (B_ * S_)        // 4096
#define EPS 1e-6f

// 1/sqrt(DH) * log2(e): folded into Q during rmsrope; softmax uses exp2f.
#define SCL2E (0.08838834764831845f * 1.4426950408889634f)

// ---------------- scratch ----------------
__device__ float g_X [(size_t)MROWS * HID];
__device__ float g_Q [(size_t)MROWS * NH * DH];
__device__ float g_K [(size_t)MROWS * NKV * DH];
__device__ float g_V [(size_t)MROWS * NKV * DH];
__device__ float g_Vt[(size_t)B_ * NKV * DH * S_];   // [b][kvh][d][s], tf32-rounded
__device__ float g_O [(size_t)MROWS * NH * DH];
__device__ float g_WqT[(size_t)HID * NH * DH];
__device__ float g_WkT[(size_t)HID * NKV * DH];
__device__ float g_WvT[(size_t)HID * NKV * DH];
__device__ float g_WoT[(size_t)NH * DH * HID];

// ---------------- helpers ----------------
__device__ __forceinline__ uint32_t smem_u32(const void* p) {
    uint32_t a;
    asm("{ .reg .u64 t; cvta.to.shared.u64 t, %1; cvt.u32.u64 %0, t; }" : "=r"(a) : "l"(p));
    return a;
}
__device__ __forceinline__ float tf32r(float x) {
    uint32_t r;
    asm("cvt.rna.tf32.f32 %0, %1;" : "=r"(r) : "f"(x));
    return __uint_as_float(r);
}
#define CP_ASYNC16(sdst, gsrc) \
    asm volatile("cp.async.cg.shared.global [%0], [%1], 16;" :: "r"(sdst), "l"(gsrc))
#define CP_COMMIT() asm volatile("cp.async.commit_group;" ::: "memory")
#define CP_WAIT(n)  asm volatile("cp.async.wait_group %0;" :: "n"(n) : "memory")

__device__ __forceinline__ void mma_tf32(float& c0, float& c1, float& c2, float& c3,
                                         uint32_t a0, uint32_t a1, uint32_t a2, uint32_t a3,
                                         uint32_t b0, uint32_t b1) {
    asm volatile(
        "mma.sync.aligned.m16n8k8.row.col.f32.tf32.tf32.f32 "
        "{%0,%1,%2,%3}, {%4,%5,%6,%7}, {%8,%9}, {%0,%1,%2,%3};"
        : "+f"(c0), "+f"(c1), "+f"(c2), "+f"(c3)
        : "r"(a0), "r"(a1), "r"(a2), "r"(a3), "r"(b0), "r"(b1));
}

// ---------------- tf32 rounding ----------------
__global__ void __launch_bounds__(256) tf32_round_kernel(float* __restrict__ dst,
                                                         const float* __restrict__ src,
                                                         size_t n4) {
    for (size_t i = blockIdx.x * blockDim.x + threadIdx.x; i < n4;
         i += (size_t)gridDim.x * blockDim.x) {
        float4 v = ((const float4*)src)[i];
        v.x = tf32r(v.x); v.y = tf32r(v.y); v.z = tf32r(v.z); v.w = tf32r(v.w);
        ((float4*)dst)[i] = v;
    }
}

// ---------------- transpose + tf32 round: dst[C][R] = tf32(src[R][C]) ----------------
__global__ void __launch_bounds__(256) transpose_tf32_kernel(float* __restrict__ dst,
                                                             const float* __restrict__ src,
                                                             int R, int C) {
    __shared__ float t[32][33];
    int bx = blockIdx.x * 32;
    int by = blockIdx.y * 32;
    int tx = threadIdx.x, ty = threadIdx.y;
#pragma unroll
    for (int i = 0; i < 4; i++)
        t[ty + i * 8][tx] = src[(size_t)(by + ty + i * 8) * C + bx + tx];
    __syncthreads();
#pragma unroll
    for (int i = 0; i < 4; i++)
        dst[(size_t)(bx + ty + i * 8) * R + by + tx] = tf32r(t[tx][ty + i * 8]);
}

// ---------------- V transpose: g_V [s][kvh][d] -> g_Vt [b][kvh][d][s] (tf32) ----------------
__global__ void __launch_bounds__(256) vtrans_kernel(float* __restrict__ dst,
                                                     const float* __restrict__ src) {
    __shared__ float t[32][33];
    const int bz = blockIdx.z;              // b*NKV + kvh
    const int b = bz >> 2, kvh = bz & 3;
    const int s0 = blockIdx.x * 32, d0 = blockIdx.y * 32;
    const int tx = threadIdx.x, ty = threadIdx.y;   // 32 x 8
#pragma unroll
    for (int i = 0; i < 4; i++)
        t[ty + i * 8][tx] =
            src[(size_t)(b * S_ + s0 + ty + i * 8) * (NKV * DH) + kvh * DH + d0 + tx];
    __syncthreads();
#pragma unroll
    for (int i = 0; i < 4; i++)
        dst[((size_t)bz * DH + d0 + ty + i * 8) * S_ + s0 + tx] = tf32r(t[tx][ty + i * 8]);
}

// ---------------- tf32 mma.sync GEMM (unchanged) ----------------
#define GK      2048
#define GM_BM   128
#define GM_BN   128
#define GM_BK   16
#define GM_LDS  20
#define GM_NST  3
#define GM_NIT  (GK / GM_BK)
#define GM_STAGE_FLOATS (2 * 128 * GM_LDS)
#define GM_SMEM_BYTES (GM_NST * GM_STAGE_FLOATS * 4)   // 61440

__device__ __forceinline__ void gm_load_stage(uint32_t sA, uint32_t sB,
                                              const float* __restrict__ Atile,
                                              const float* __restrict__ Btile,
                                              int tid) {
#pragma unroll
    for (int i = 0; i < 2; i++) {
        int idx = i * 256 + tid;
        int r = idx >> 2, c = idx & 3;
        CP_ASYNC16(sA + (uint32_t)(r * (GM_LDS * 4) + c * 16),
                   Atile + (size_t)r * GK + c * 4);
    }
#pragma unroll
    for (int i = 0; i < 2; i++) {
        int idx = i * 256 + tid;
        int r = idx >> 2, c = idx & 3;
        CP_ASYNC16(sB + (uint32_t)(r * (GM_LDS * 4) + c * 16),
                   Btile + (size_t)r * GK + c * 4);
    }
    CP_COMMIT();
}

__global__ void __launch_bounds__(256, 1) gemm_tf32mma_kernel(
    const float* __restrict__ A, const float* __restrict__ Bt,
    float* __restrict__ C, int M, int N)
{
    extern __shared__ float gsm[];
    const uint32_t sbase = smem_u32(gsm);
    const int tid = threadIdx.x;
    const int wid = tid >> 5, lid = tid & 31;
    const int wm = wid >> 1;
    const int wn = wid & 1;
    const int gid = lid >> 2;
    const int tig = lid & 3;
    const int bm = blockIdx.y * GM_BM;
    const int bn = blockIdx.x * GM_BN;

    float acc[2][8][4];
#pragma unroll
    for (int mt = 0; mt < 2; mt++)
#pragma unroll
        for (int nt = 0; nt < 8; nt++)
#pragma unroll
            for (int q = 0; q < 4; q++) acc[mt][nt][q] = 0.f;

    const float* Abase = A + (size_t)bm * GK;
    const float* Bbase = Bt + (size_t)bn * GK;

    uint32_t stA[GM_NST], stB[GM_NST];
#pragma unroll
    for (int s = 0; s < GM_NST; s++) {
        stA[s] = sbase + (uint32_t)(s * GM_STAGE_FLOATS * 4);
        stB[s] = stA[s] + 128u * GM_LDS * 4u;
    }

    gm_load_stage(stA[0], stB[0], Abase, Bbase, tid);
    gm_load_stage(stA[1], stB[1], Abase + GM_BK, Bbase + GM_BK, tid);

    const float* As0;
    const float* Bs0;

    for (int it = 0; it < GM_NIT; it++) {
        CP_WAIT(1);
        __syncthreads();

        const int ki = it + 2;
        if (ki < GM_NIT) {
            const int b = ki % GM_NST;
            gm_load_stage(stA[b], stB[b], Abase + ki * GM_BK, Bbase + ki * GM_BK, tid);
        }

        const int s = it % GM_NST;
        As0 = gsm + (size_t)s * GM_STAGE_FLOATS;
        Bs0 = As0 + 128 * GM_LDS;

#pragma unroll
        for (int k0 = 0; k0 < GM_BK; k0 += 8) {
            uint32_t af[2][4];
#pragma unroll
            for (int mt = 0; mt < 2; mt++) {
                int r = wm * 32 + mt * 16 + gid;
                af[mt][0] = __float_as_uint(As0[r * GM_LDS + k0 + tig]);
                af[mt][1] = __float_as_uint(As0[(r + 8) * GM_LDS + k0 + tig]);
                af[mt][2] = __float_as_uint(As0[r * GM_LDS + k0 + tig + 4]);
                af[mt][3] = __float_as_uint(As0[(r + 8) * GM_LDS + k0 + tig + 4]);
            }
#pragma unroll
            for (int nt = 0; nt < 8; nt++) {
                int rn = wn * 64 + nt * 8 + gid;
                uint32_t b0 = __float_as_uint(Bs0[rn * GM_LDS + k0 + tig]);
                uint32_t b1 = __float_as_uint(Bs0[rn * GM_LDS + k0 + tig + 4]);
#pragma unroll
                for (int mt = 0; mt < 2; mt++)
                    mma_tf32(acc[mt][nt][0], acc[mt][nt][1], acc[mt][nt][2], acc[mt][nt][3],
                             af[mt][0], af[mt][1], af[mt][2], af[mt][3], b0, b1);
            }
        }
    }

#pragma unroll
    for (int mt = 0; mt < 2; mt++) {
        int r0 = bm + wm * 32 + mt * 16 + gid;
#pragma unroll
        for (int nt = 0; nt < 8; nt++) {
            int c = bn + wn * 64 + nt * 8 + tig * 2;
            float2 v0 = make_float2(acc[mt][nt][0], acc[mt][nt][1]);
            float2 v1 = make_float2(acc[mt][nt][2], acc[mt][nt][3]);
            *(float2*)(C + (size_t)r0 * N + c)       = v0;
            *(float2*)(C + (size_t)(r0 + 8) * N + c) = v1;
        }
    }
}

// ---------------- fused RMSNorm + RoPE (tf32-rounded output, optional scale) ----------------
__global__ void __launch_bounds__(128) rmsrope_kernel(
    float* __restrict__ buf, const float* __restrict__ w,
    const float* __restrict__ cosb, const float* __restrict__ sinb, int nheads,
    float oscale)
{
    const int bh  = blockIdx.x;
    const int row = bh / nheads;
    const int h   = bh - row * nheads;
    const int s   = row & (S_ - 1);
    const int d   = threadIdx.x;

    float* p = buf + ((size_t)row * nheads + h) * DH;
    float v = p[d];

    float ss = v * v;
#pragma unroll
    for (int o = 16; o > 0; o >>= 1) ss += __shfl_xor_sync(0xffffffffu, ss, o);
    __shared__ float sh[4];
    if ((d & 31) == 0) sh[d >> 5] = ss;
    __syncthreads();
    float tot = sh[0] + sh[1] + sh[2] + sh[3];
    float inv = rsqrtf(tot * (1.0f / DH) + EPS);

    int pd = d ^ 64;
    float pv  = p[pd];
    float nv  = w[d]  * v  * inv;
    float npv = w[pd] * pv * inv;
    float c  = cosb[(size_t)s * DH + d];
    float sn = sinb[(size_t)s * DH + d];
    float out = nv * c + ((d < 64) ? -npv : npv) * sn;
    __syncthreads();
    p[d] = tf32r(out * oscale);
}

// ---------------- tensor-core flash attention v2 (fixed tile loads) ----------------
// BM=128 q rows, BN=64 kv cols, 256 threads = 8 warps x 16 rows.
// Q pre-scaled by 1/sqrt(d)*log2e (rmsrope); softmax in exp2 domain.
// K/V tiles double-buffered via cp.async; V pre-transposed globally (g_Vt).
// P C-frag -> A-frag via quad shfls (no smem round trip).
#define FKP 132
#define FVP 68
#define FQ_OFF 0
#define FK_OFF (128 * FKP)                   // 16896 floats
#define FV_OFF (FK_OFF + 2 * 64 * FKP)       // 33792 floats
#define FT_FLOATS (FV_OFF + 2 * 128 * FVP)   // 51200 floats
#define FT_BYTES (FT_FLOATS * 4)             // 204800 bytes

__global__ void __launch_bounds__(256, 1) flash_tc2_kernel(
    const float* __restrict__ Qg, const float* __restrict__ Kg,
    const float* __restrict__ Vt, float* __restrict__ Og)
{
    extern __shared__ float fsm[];
    const uint32_t sb = smem_u32(fsm);

    const int qt  = (int)gridDim.x - 1 - (int)blockIdx.x;   // long blocks first
    const int h   = blockIdx.y;
    const int b   = blockIdx.z;
    const int kvh = h >> 2;
    const int tid = threadIdx.x;
    const int wid = tid >> 5, lid = tid & 31;
    const int gid = lid >> 2, tig = lid & 3;

    const int r1loc = wid * 16 + gid;
    const int r2loc = r1loc + 8;
    const int r1g = qt * 128 + r1loc;
    const int r2g = r1g + 8;

    const float* Kbase  = Kg + (size_t)(b * S_) * (NKV * DH) + (size_t)kvh * DH;
    const float* Vtbase = Vt + ((size_t)(b * NKV + kvh) * DH) * S_;

    // Q tile: 128 rows x 32 float4-chunks = 4096 chunks
    {
        const size_t qbase = ((size_t)(b * S_ + qt * 128)) * (NH * DH) + (size_t)h * DH;
#pragma unroll
        for (int t = 0; t < 16; t++) {
            int i = tid + t * 256;
            int m = i >> 5, c = i & 31;
            CP_ASYNC16(sb + (uint32_t)((FQ_OFF + m * FKP + c * 4) * 4),
                       Qg + qbase + (size_t)m * (NH * DH) + c * 4);
        }
    }
    // K tile 0: 64 rows x 32 chunks = 2048 chunks
#pragma unroll
    for (int t = 0; t < 8; t++) {
        int i = tid + t * 256;
        int n = i >> 5, c = i & 31;
        CP_ASYNC16(sb + (uint32_t)((FK_OFF + n * FKP + c * 4) * 4),
                   Kbase + (size_t)n * (NKV * DH) + c * 4);
    }
    // V tile 0: 128 d-rows x 16 chunks (64 kv floats) = 2048 chunks
#pragma unroll
    for (int t = 0; t < 8; t++) {
        int i = tid + t * 256;
        int d = i >> 4, c = i & 15;
        CP_ASYNC16(sb + (uint32_t)((FV_OFF + d * FVP + c * 4) * 4),
                   Vtbase + (size_t)d * S_ + c * 4);
    }
    CP_COMMIT();

    float oacc[16][4];
#pragma unroll
    for (int db = 0; db < 16; db++)
#pragma unroll
        for (int q = 0; q < 4; q++) oacc[db][q] = 0.f;
    float m1 = -1e30f, m2 = -1e30f, l1 = 0.f, l2 = 0.f;

    const int ntiles = 2 * qt + 2;
    for (int j = 0; j < ntiles; j++) {
        CP_WAIT(0);
        __syncthreads();

        // prefetch tile j+1 into the other buffer (overlaps compute of tile j)
        if (j + 1 < ntiles) {
            const int nb_ = (j + 1) & 1;
            const uint32_t kd = sb + (uint32_t)((FK_OFF + nb_ * 64 * FKP) * 4);
            const uint32_t vd = sb + (uint32_t)((FV_OFF + nb_ * 128 * FVP) * 4);
#pragma unroll
            for (int t = 0; t < 8; t++) {
                int i = tid + t * 256;
                int n = i >> 5, c = i & 31;
                CP_ASYNC16(kd + (uint32_t)((n * FKP + c * 4) * 4),
                           Kbase + (size_t)((j + 1) * 64 + n) * (NKV * DH) + c * 4);
            }
#pragma unroll
            for (int t = 0; t < 8; t++) {
                int i = tid + t * 256;
                int d = i >> 4, c = i & 15;
                CP_ASYNC16(vd + (uint32_t)((d * FVP + c * 4) * 4),
                           Vtbase + (size_t)d * S_ + (j + 1) * 64 + c * 4);
            }
            CP_COMMIT();
        }

        const float* Qsb = fsm;
        const float* Ksb = fsm + FK_OFF + (j & 1) * 64 * FKP;
        const float* Vsb = fsm + FV_OFF + (j & 1) * 128 * FVP;

        // S = Q @ K^T (scores already in log2 domain via pre-scaled Q)
        float sacc[8][4];
#pragma unroll
        for (int nb = 0; nb < 8; nb++)
#pragma unroll
            for (int q = 0; q < 4; q++) sacc[nb][q] = 0.f;

#pragma unroll
        for (int ks = 0; ks < 16; ks++) {
            int k0 = ks * 8;
            uint32_t a0 = __float_as_uint(Qsb[r1loc * FKP + k0 + tig]);
            uint32_t a1 = __float_as_uint(Qsb[r2loc * FKP + k0 + tig]);
            uint32_t a2 = __float_as_uint(Qsb[r1loc * FKP + k0 + tig + 4]);
            uint32_t a3 = __float_as_uint(Qsb[r2loc * FKP + k0 + tig + 4]);
#pragma unroll
            for (int nb = 0; nb < 8; nb++) {
                uint32_t b0 = __float_as_uint(Ksb[(nb * 8 + gid) * FKP + k0 + tig]);
                uint32_t b1 = __float_as_uint(Ksb[(nb * 8 + gid) * FKP + k0 + tig + 4]);
                mma_tf32(sacc[nb][0], sacc[nb][1], sacc[nb][2], sacc[nb][3],
                         a0, a1, a2, a3, b0, b1);
            }
        }

        // causal mask (only last two tiles can cross the diagonal)
        if (j >= 2 * qt) {
#pragma unroll
            for (int nb = 0; nb < 8; nb++) {
                int c0g = j * 64 + nb * 8 + tig * 2;
                if (c0g > r1g)     sacc[nb][0] = -1e30f;
                if (c0g + 1 > r1g) sacc[nb][1] = -1e30f;
                if (c0g > r2g)     sacc[nb][2] = -1e30f;
                if (c0g + 1 > r2g) sacc[nb][3] = -1e30f;
            }
        }

        // row max over quad
        float mx1 = -1e30f, mx2 = -1e30f;
#pragma unroll
        for (int nb = 0; nb < 8; nb++) {
            mx1 = fmaxf(mx1, fmaxf(sacc[nb][0], sacc[nb][1]));
            mx2 = fmaxf(mx2, fmaxf(sacc[nb][2], sacc[nb][3]));
        }
        mx1 = fmaxf(mx1, __shfl_xor_sync(0xffffffffu, mx1, 1));
        mx1 = fmaxf(mx1, __shfl_xor_sync(0xffffffffu, mx1, 2));
        mx2 = fmaxf(mx2, __shfl_xor_sync(0xffffffffu, mx2, 1));
        mx2 = fmaxf(mx2, __shfl_xor_sync(0xffffffffu, mx2, 2));

        float mn1 = fmaxf(m1, mx1), mn2 = fmaxf(m2, mx2);
        float f1 = exp2f(m1 - mn1), f2 = exp2f(m2 - mn2);
        m1 = mn1; m2 = mn2;

        // probs (tf32-rounded, kept in sacc) + row sums
        float ls1 = 0.f, ls2 = 0.f;
#pragma unroll
        for (int nb = 0; nb < 8; nb++) {
            float p0 = tf32r(exp2f(sacc[nb][0] - mn1));
            float p1 = tf32r(exp2f(sacc[nb][1] - mn1));
            float p2 = tf32r(exp2f(sacc[nb][2] - mn2));
            float p3 = tf32r(exp2f(sacc[nb][3] - mn2));
            sacc[nb][0] = p0; sacc[nb][1] = p1;
            sacc[nb][2] = p2; sacc[nb][3] = p3;
            ls1 += p0 + p1;
            ls2 += p2 + p3;
        }
        ls1 += __shfl_xor_sync(0xffffffffu, ls1, 1);
        ls1 += __shfl_xor_sync(0xffffffffu, ls1, 2);
        ls2 += __shfl_xor_sync(0xffffffffu, ls2, 1);
        ls2 += __shfl_xor_sync(0xffffffffu, ls2, 2);
        l1 = l1 * f1 + ls1;
        l2 = l2 * f2 + ls2;

#pragma unroll
        for (int db = 0; db < 16; db++) {
            oacc[db][0] *= f1; oacc[db][1] *= f1;
            oacc[db][2] *= f2; oacc[db][3] *= f2;
        }

        // O += P @ V.  A-frag built from sacc via quad shfls (C->A layout permutation).
        const int s2 = tig >> 1;
        const bool odd = (tig & 1);
#pragma unroll
        for (int ks = 0; ks < 8; ks++) {
            float e, o;
            e = __shfl_sync(0xffffffffu, sacc[ks][0], s2, 4);
            o = __shfl_sync(0xffffffffu, sacc[ks][1], s2, 4);
            float a0f = odd ? o : e;
            e = __shfl_sync(0xffffffffu, sacc[ks][0], s2 + 2, 4);
            o = __shfl_sync(0xffffffffu, sacc[ks][1], s2 + 2, 4);
            float a2f = odd ? o : e;
            e = __shfl_sync(0xffffffffu, sacc[ks][2], s2, 4);
            o = __shfl_sync(0xffffffffu, sacc[ks][3], s2, 4);
            float a1f = odd ? o : e;
            e = __shfl_sync(0xffffffffu, sacc[ks][2], s2 + 2, 4);
            o = __shfl_sync(0xffffffffu, sacc[ks][3], s2 + 2, 4);
            float a3f = odd ? o : e;

            uint32_t a0 = __float_as_uint(a0f);
            uint32_t a1 = __float_as_uint(a1f);
            uint32_t a2 = __float_as_uint(a2f);
            uint32_t a3 = __float_as_uint(a3f);
            int k0 = ks * 8;
#pragma unroll
            for (int db = 0; db < 16; db++) {
                uint32_t b0 = __float_as_uint(Vsb[(db * 8 + gid) * FVP + k0 + tig]);
                uint32_t b1 = __float_as_uint(Vsb[(db * 8 + gid) * FVP + k0 + tig + 4]);
                mma_tf32(oacc[db][0], oacc[db][1], oacc[db][2], oacc[db][3],
                         a0, a1, a2, a3, b0, b1);
            }
        }
    }

    // epilogue: normalize, tf32-round (feeds O-proj GEMM), write
    const float inv1 = 1.0f / l1, inv2 = 1.0f / l2;
    const size_t obase = ((size_t)(b * S_ + qt * 128)) * (NH * DH) + (size_t)h * DH;
#pragma unroll
    for (int db = 0; db < 16; db++) {
        int c = db * 8 + tig * 2;
        *(float2*)(Og + obase + (size_t)r1loc * (NH * DH) + c) =
            make_float2(tf32r(oacc[db][0] * inv1), tf32r(oacc[db][1] * inv1));
        *(float2*)(Og + obase + (size_t)r2loc * (NH * DH) + c) =
            make_float2(tf32r(oacc[db][2] * inv2), tf32r(oacc[db][3] * inv2));
    }
}

// ---------------- launch ----------------
extern "C" void kernel_launch(void* const* d_in, const int* in_sizes, int n_in,
                              void* d_out, int out_size)
{
    const float* X    = (const float*)d_in[0];
    // d_in[1] = attention_mask: exact causal mask, applied analytically — unused
    const float* cosp = (const float*)d_in[2];
    const float* sinp = (const float*)d_in[3];
    const float* Wq   = (const float*)d_in[4];
    const float* Wk   = (const float*)d_in[5];
    const float* Wv   = (const float*)d_in[6];
    const float* Wo   = (const float*)d_in[7];
    const float* qnw  = (const float*)d_in[8];
    const float* knw  = (const float*)d_in[9];
    float* out = (float*)d_out;

    float *Xr, *Q, *K, *V, *VtP, *O, *WqT, *WkT, *WvT, *WoT;
    cudaGetSymbolAddress((void**)&Xr,  g_X);
    cudaGetSymbolAddress((void**)&Q,   g_Q);
    cudaGetSymbolAddress((void**)&K,   g_K);
    cudaGetSymbolAddress((void**)&V,   g_V);
    cudaGetSymbolAddress((void**)&VtP, g_Vt);
    cudaGetSymbolAddress((void**)&O,   g_O);
    cudaGetSymbolAddress((void**)&WqT, g_WqT);
    cudaGetSymbolAddress((void**)&WkT, g_WkT);
    cudaGetSymbolAddress((void**)&WvT, g_WvT);
    cudaGetSymbolAddress((void**)&WoT, g_WoT);

    cudaFuncSetAttribute(gemm_tf32mma_kernel, cudaFuncAttributeMaxDynamicSharedMemorySize,
                         GM_SMEM_BYTES);
    cudaFuncSetAttribute(flash_tc2_kernel, cudaFuncAttributeMaxDynamicSharedMemorySize,
                         FT_BYTES);

    // tf32-round X; transpose+round weights
    tf32_round_kernel<<<2048, 256>>>(Xr, X, (size_t)MROWS * HID / 4);
    transpose_tf32_kernel<<<dim3((NH * DH) / 32, HID / 32), dim3(32, 8)>>>(WqT, Wq, HID, NH * DH);
    transpose_tf32_kernel<<<dim3((NKV * DH) / 32, HID / 32), dim3(32, 8)>>>(WkT, Wk, HID, NKV * DH);
    transpose_tf32_kernel<<<dim3((NKV * DH) / 32, HID / 32), dim3(32, 8)>>>(WvT, Wv, HID, NKV * DH);
    transpose_tf32_kernel<<<dim3(HID / 32, (NH * DH) / 32), dim3(32, 8)>>>(WoT, Wo, NH * DH, HID);

    // QKV projections (tensor cores)
    gemm_tf32mma_kernel<<<dim3(NH * DH / GM_BN, MROWS / GM_BM), 256, GM_SMEM_BYTES>>>(
        Xr, WqT, Q, MROWS, NH * DH);
    gemm_tf32mma_kernel<<<dim3(NKV * DH / GM_BN, MROWS / GM_BM), 256, GM_SMEM_BYTES>>>(
        Xr, WkT, K, MROWS, NKV * DH);
    gemm_tf32mma_kernel<<<dim3(NKV * DH / GM_BN, MROWS / GM_BM), 256, GM_SMEM_BYTES>>>(
        Xr, WvT, V, MROWS, NKV * DH);

    // RMSNorm + RoPE: Q pre-scaled into log2-softmax domain; K plain; V transposed+rounded
    rmsrope_kernel<<<MROWS * NH, 128>>>(Q, qnw, cosp, sinp, NH, SCL2E);
    rmsrope_kernel<<<MROWS * NKV, 128>>>(K, knw, cosp, sinp, NKV, 1.0f);
    vtrans_kernel<<<dim3(S_ / 32, DH / 32, B_ * NKV), dim3(32, 8)>>>(VtP, V);

    // Flash attention v2 (tensor cores, pipelined)
    flash_tc2_kernel<<<dim3(S_ / 128, NH, B_), 256, FT_BYTES>>>(Q, K, VtP, O);

    // O-projection (tensor cores)
    gemm_tf32mma_kernel<<<dim3(HID / GM_BN, MROWS / GM_BM), 256, GM_SMEM_BYTES>>>(
        O, WoT, out, MROWS, HID);
}

// round 9
// speedup vs baseline: 3.3178x; 1.0136x over previous
#include <cuda_runtime.h>
#include <cuda_bf16.h>
#include <math.h>
#include <stdint.h>

// Problem constants
#define B_  2
#define S_  2048
#define HID 2048
#define NH  16
#define NKV 4
#define DH  128
#define MROWS (B_ * S_)        // 4096
#define EPS 1e-6f

// packed QKV layout: [row][ Q(0..2047) | K(2048..2559) | V(2560..3071) ]
#define QKVS 3072
#define KOFF 2048
#define VOFF 2560

// 1/sqrt(DH) * log2(e): folded into Q during rmsrope; softmax uses exp2f.
#define SCL2E (0.08838834764831845f * 1.4426950408889634f)

// ---------------- scratch ----------------
__device__ float g_X   [(size_t)MROWS * HID];
__device__ float g_QKV [(size_t)MROWS * QKVS];      // packed Q|K|V
__device__ float g_Vt  [(size_t)B_ * NKV * DH * S_]; // [b][kvh][d][s], tf32-rounded
__device__ float g_O   [(size_t)MROWS * NH * DH];
__device__ float g_WqkvT[(size_t)QKVS * HID];        // [N=3072][K=2048]
__device__ float g_WoT [(size_t)NH * DH * HID];

// ---------------- helpers ----------------
__device__ __forceinline__ uint32_t smem_u32(const void* p) {
    uint32_t a;
    asm("{ .reg .u64 t; cvta.to.shared.u64 t, %1; cvt.u32.u64 %0, t; }" : "=r"(a) : "l"(p));
    return a;
}
__device__ __forceinline__ float tf32r(float x) {
    uint32_t r;
    asm("cvt.rna.tf32.f32 %0, %1;" : "=r"(r) : "f"(x));
    return __uint_as_float(r);
}
#define CP_ASYNC16(sdst, gsrc) \
    asm volatile("cp.async.cg.shared.global [%0], [%1], 16;" :: "r"(sdst), "l"(gsrc))
#define CP_COMMIT() asm volatile("cp.async.commit_group;" ::: "memory")
#define CP_WAIT(n)  asm volatile("cp.async.wait_group %0;" :: "n"(n) : "memory")

__device__ __forceinline__ void mma_tf32(float& c0, float& c1, float& c2, float& c3,
                                         uint32_t a0, uint32_t a1, uint32_t a2, uint32_t a3,
                                         uint32_t b0, uint32_t b1) {
    asm volatile(
        "mma.sync.aligned.m16n8k8.row.col.f32.tf32.tf32.f32 "
        "{%0,%1,%2,%3}, {%4,%5,%6,%7}, {%8,%9}, {%0,%1,%2,%3};"
        : "+f"(c0), "+f"(c1), "+f"(c2), "+f"(c3)
        : "r"(a0), "r"(a1), "r"(a2), "r"(a3), "r"(b0), "r"(b1));
}

// ---------------- tf32 rounding ----------------
__global__ void __launch_bounds__(256) tf32_round_kernel(float* __restrict__ dst,
                                                         const float* __restrict__ src,
                                                         size_t n4) {
    for (size_t i = blockIdx.x * blockDim.x + threadIdx.x; i < n4;
         i += (size_t)gridDim.x * blockDim.x) {
        float4 v = ((const float4*)src)[i];
        v.x = tf32r(v.x); v.y = tf32r(v.y); v.z = tf32r(v.z); v.w = tf32r(v.w);
        ((float4*)dst)[i] = v;
    }
}

// ---------------- transpose + tf32 round: dst[C][R] = tf32(src[R][C]) ----------------
__global__ void __launch_bounds__(256) transpose_tf32_kernel(float* __restrict__ dst,
                                                             const float* __restrict__ src,
                                                             int R, int C) {
    __shared__ float t[32][33];
    int bx = blockIdx.x * 32;
    int by = blockIdx.y * 32;
    int tx = threadIdx.x, ty = threadIdx.y;
#pragma unroll
    for (int i = 0; i < 4; i++)
        t[ty + i * 8][tx] = src[(size_t)(by + ty + i * 8) * C + bx + tx];
    __syncthreads();
#pragma unroll
    for (int i = 0; i < 4; i++)
        dst[(size_t)(bx + ty + i * 8) * R + by + tx] = tf32r(t[tx][ty + i * 8]);
}

// ---------------- V transpose from packed QKV -> g_Vt [b][kvh][d][s] (tf32) ----------------
__global__ void __launch_bounds__(256) vtrans_kernel(float* __restrict__ dst,
                                                     const float* __restrict__ src) {
    __shared__ float t[32][33];
    const int bz = blockIdx.z;              // b*NKV + kvh
    const int b = bz >> 2, kvh = bz & 3;
    const int s0 = blockIdx.x * 32, d0 = blockIdx.y * 32;
    const int tx = threadIdx.x, ty = threadIdx.y;   // 32 x 8
#pragma unroll
    for (int i = 0; i < 4; i++)
        t[ty + i * 8][tx] =
            src[(size_t)(b * S_ + s0 + ty + i * 8) * QKVS + VOFF + kvh * DH + d0 + tx];
    __syncthreads();
#pragma unroll
    for (int i = 0; i < 4; i++)
        dst[((size_t)bz * DH + d0 + ty + i * 8) * S_ + s0 + tx] = tf32r(t[tx][ty + i * 8]);
}

// ---------------- tf32 mma.sync GEMM ----------------
#define GK      2048
#define GM_BM   128
#define GM_BN   128
#define GM_BK   16
#define GM_LDS  20
#define GM_NST  3
#define GM_NIT  (GK / GM_BK)
#define GM_STAGE_FLOATS (2 * 128 * GM_LDS)
#define GM_SMEM_BYTES (GM_NST * GM_STAGE_FLOATS * 4)   // 61440

__device__ __forceinline__ void gm_load_stage(uint32_t sA, uint32_t sB,
                                              const float* __restrict__ Atile,
                                              const float* __restrict__ Btile,
                                              int tid) {
#pragma unroll
    for (int i = 0; i < 2; i++) {
        int idx = i * 256 + tid;
        int r = idx >> 2, c = idx & 3;
        CP_ASYNC16(sA + (uint32_t)(r * (GM_LDS * 4) + c * 16),
                   Atile + (size_t)r * GK + c * 4);
    }
#pragma unroll
    for (int i = 0; i < 2; i++) {
        int idx = i * 256 + tid;
        int r = idx >> 2, c = idx & 3;
        CP_ASYNC16(sB + (uint32_t)(r * (GM_LDS * 4) + c * 16),
                   Btile + (size_t)r * GK + c * 4);
    }
    CP_COMMIT();
}

__global__ void __launch_bounds__(256, 1) gemm_tf32mma_kernel(
    const float* __restrict__ A, const float* __restrict__ Bt,
    float* __restrict__ C, int M, int N)
{
    extern __shared__ float gsm[];
    const uint32_t sbase = smem_u32(gsm);
    const int tid = threadIdx.x;
    const int wid = tid >> 5, lid = tid & 31;
    const int wm = wid >> 1;
    const int wn = wid & 1;
    const int gid = lid >> 2;
    const int tig = lid & 3;
    const int bm = blockIdx.y * GM_BM;
    const int bn = blockIdx.x * GM_BN;

    float acc[2][8][4];
#pragma unroll
    for (int mt = 0; mt < 2; mt++)
#pragma unroll
        for (int nt = 0; nt < 8; nt++)
#pragma unroll
            for (int q = 0; q < 4; q++) acc[mt][nt][q] = 0.f;

    const float* Abase = A + (size_t)bm * GK;
    const float* Bbase = Bt + (size_t)bn * GK;

    uint32_t stA[GM_NST], stB[GM_NST];
#pragma unroll
    for (int s = 0; s < GM_NST; s++) {
        stA[s] = sbase + (uint32_t)(s * GM_STAGE_FLOATS * 4);
        stB[s] = stA[s] + 128u * GM_LDS * 4u;
    }

    gm_load_stage(stA[0], stB[0], Abase, Bbase, tid);
    gm_load_stage(stA[1], stB[1], Abase + GM_BK, Bbase + GM_BK, tid);

    const float* As0;
    const float* Bs0;

    for (int it = 0; it < GM_NIT; it++) {
        CP_WAIT(1);
        __syncthreads();

        const int ki = it + 2;
        if (ki < GM_NIT) {
            const int b = ki % GM_NST;
            gm_load_stage(stA[b], stB[b], Abase + ki * GM_BK, Bbase + ki * GM_BK, tid);
        }

        const int s = it % GM_NST;
        As0 = gsm + (size_t)s * GM_STAGE_FLOATS;
        Bs0 = As0 + 128 * GM_LDS;

#pragma unroll
        for (int k0 = 0; k0 < GM_BK; k0 += 8) {
            uint32_t af[2][4];
#pragma unroll
            for (int mt = 0; mt < 2; mt++) {
                int r = wm * 32 + mt * 16 + gid;
                af[mt][0] = __float_as_uint(As0[r * GM_LDS + k0 + tig]);
                af[mt][1] = __float_as_uint(As0[(r + 8) * GM_LDS + k0 + tig]);
                af[mt][2] = __float_as_uint(As0[r * GM_LDS + k0 + tig + 4]);
                af[mt][3] = __float_as_uint(As0[(r + 8) * GM_LDS + k0 + tig + 4]);
            }
#pragma unroll
            for (int nt = 0; nt < 8; nt++) {
                int rn = wn * 64 + nt * 8 + gid;
                uint32_t b0 = __float_as_uint(Bs0[rn * GM_LDS + k0 + tig]);
                uint32_t b1 = __float_as_uint(Bs0[rn * GM_LDS + k0 + tig + 4]);
#pragma unroll
                for (int mt = 0; mt < 2; mt++)
                    mma_tf32(acc[mt][nt][0], acc[mt][nt][1], acc[mt][nt][2], acc[mt][nt][3],
                             af[mt][0], af[mt][1], af[mt][2], af[mt][3], b0, b1);
            }
        }
    }

#pragma unroll
    for (int mt = 0; mt < 2; mt++) {
        int r0 = bm + wm * 32 + mt * 16 + gid;
#pragma unroll
        for (int nt = 0; nt < 8; nt++) {
            int c = bn + wn * 64 + nt * 8 + tig * 2;
            float2 v0 = make_float2(acc[mt][nt][0], acc[mt][nt][1]);
            float2 v1 = make_float2(acc[mt][nt][2], acc[mt][nt][3]);
            *(float2*)(C + (size_t)r0 * N + c)       = v0;
            *(float2*)(C + (size_t)(r0 + 8) * N + c) = v1;
        }
    }
}

// ---------------- fused RMSNorm + RoPE on packed buffer ----------------
// p = buf + row*rowstride + hoff + h*DH
__global__ void __launch_bounds__(128) rmsrope_kernel(
    float* __restrict__ buf, const float* __restrict__ w,
    const float* __restrict__ cosb, const float* __restrict__ sinb, int nheads,
    float oscale, int rowstride, int hoff)
{
    const int bh  = blockIdx.x;
    const int row = bh / nheads;
    const int h   = bh - row * nheads;
    const int s   = row & (S_ - 1);
    const int d   = threadIdx.x;

    float* p = buf + (size_t)row * rowstride + hoff + h * DH;
    float v = p[d];

    float ss = v * v;
#pragma unroll
    for (int o = 16; o > 0; o >>= 1) ss += __shfl_xor_sync(0xffffffffu, ss, o);
    __shared__ float sh[4];
    if ((d & 31) == 0) sh[d >> 5] = ss;
    __syncthreads();
    float tot = sh[0] + sh[1] + sh[2] + sh[3];
    float inv = rsqrtf(tot * (1.0f / DH) + EPS);

    int pd = d ^ 64;
    float pv  = p[pd];
    float nv  = w[d]  * v  * inv;
    float npv = w[pd] * pv * inv;
    float c  = cosb[(size_t)s * DH + d];
    float sn = sinb[(size_t)s * DH + d];
    float out = nv * c + ((d < 64) ? -npv : npv) * sn;
    __syncthreads();
    p[d] = tf32r(out * oscale);
}

// ---------------- tensor-core flash attention v3 ----------------
// Reads Q/K from the packed QKV buffer (stride QKVS); V from g_Vt.
// Adds warp-uniform rescale skip when the running max is unchanged.
#define FKP 132
#define FVP 68
#define FQ_OFF 0
#define FK_OFF (128 * FKP)                   // 16896 floats
#define FV_OFF (FK_OFF + 2 * 64 * FKP)       // 33792 floats
#define FT_FLOATS (FV_OFF + 2 * 128 * FVP)   // 51200 floats
#define FT_BYTES (FT_FLOATS * 4)             // 204800 bytes

__global__ void __launch_bounds__(256, 1) flash_tc3_kernel(
    const float* __restrict__ QKV, const float* __restrict__ Vt,
    float* __restrict__ Og)
{
    extern __shared__ float fsm[];
    const uint32_t sb = smem_u32(fsm);

    const int qt  = (int)gridDim.x - 1 - (int)blockIdx.x;   // long blocks first
    const int h   = blockIdx.y;
    const int b   = blockIdx.z;
    const int kvh = h >> 2;
    const int tid = threadIdx.x;
    const int wid = tid >> 5, lid = tid & 31;
    const int gid = lid >> 2, tig = lid & 3;

    const int r1loc = wid * 16 + gid;
    const int r2loc = r1loc + 8;
    const int r1g = qt * 128 + r1loc;
    const int r2g = r1g + 8;

    const float* Kbase  = QKV + (size_t)(b * S_) * QKVS + KOFF + (size_t)kvh * DH;
    const float* Vtbase = Vt + ((size_t)(b * NKV + kvh) * DH) * S_;

    // Q tile: 128 rows x 32 float4-chunks = 4096 chunks
    {
        const float* Qb = QKV + (size_t)(b * S_ + qt * 128) * QKVS + (size_t)h * DH;
#pragma unroll
        for (int t = 0; t < 16; t++) {
            int i = tid + t * 256;
            int m = i >> 5, c = i & 31;
            CP_ASYNC16(sb + (uint32_t)((FQ_OFF + m * FKP + c * 4) * 4),
                       Qb + (size_t)m * QKVS + c * 4);
        }
    }
    // K tile 0
#pragma unroll
    for (int t = 0; t < 8; t++) {
        int i = tid + t * 256;
        int n = i >> 5, c = i & 31;
        CP_ASYNC16(sb + (uint32_t)((FK_OFF + n * FKP + c * 4) * 4),
                   Kbase + (size_t)n * QKVS + c * 4);
    }
    // V tile 0
#pragma unroll
    for (int t = 0; t < 8; t++) {
        int i = tid + t * 256;
        int d = i >> 4, c = i & 15;
        CP_ASYNC16(sb + (uint32_t)((FV_OFF + d * FVP + c * 4) * 4),
                   Vtbase + (size_t)d * S_ + c * 4);
    }
    CP_COMMIT();

    float oacc[16][4];
#pragma unroll
    for (int db = 0; db < 16; db++)
#pragma unroll
        for (int q = 0; q < 4; q++) oacc[db][q] = 0.f;
    float m1 = -1e30f, m2 = -1e30f, l1 = 0.f, l2 = 0.f;

    const int ntiles = 2 * qt + 2;
    for (int j = 0; j < ntiles; j++) {
        CP_WAIT(0);
        __syncthreads();

        // prefetch tile j+1 into the other buffer
        if (j + 1 < ntiles) {
            const int nb_ = (j + 1) & 1;
            const uint32_t kd = sb + (uint32_t)((FK_OFF + nb_ * 64 * FKP) * 4);
            const uint32_t vd = sb + (uint32_t)((FV_OFF + nb_ * 128 * FVP) * 4);
#pragma unroll
            for (int t = 0; t < 8; t++) {
                int i = tid + t * 256;
                int n = i >> 5, c = i & 31;
                CP_ASYNC16(kd + (uint32_t)((n * FKP + c * 4) * 4),
                           Kbase + (size_t)((j + 1) * 64 + n) * QKVS + c * 4);
            }
#pragma unroll
            for (int t = 0; t < 8; t++) {
                int i = tid + t * 256;
                int d = i >> 4, c = i & 15;
                CP_ASYNC16(vd + (uint32_t)((d * FVP + c * 4) * 4),
                           Vtbase + (size_t)d * S_ + (j + 1) * 64 + c * 4);
            }
            CP_COMMIT();
        }

        const float* Qsb = fsm;
        const float* Ksb = fsm + FK_OFF + (j & 1) * 64 * FKP;
        const float* Vsb = fsm + FV_OFF + (j & 1) * 128 * FVP;

        // S = Q @ K^T
        float sacc[8][4];
#pragma unroll
        for (int nb = 0; nb < 8; nb++)
#pragma unroll
            for (int q = 0; q < 4; q++) sacc[nb][q] = 0.f;

#pragma unroll
        for (int ks = 0; ks < 16; ks++) {
            int k0 = ks * 8;
            uint32_t a0 = __float_as_uint(Qsb[r1loc * FKP + k0 + tig]);
            uint32_t a1 = __float_as_uint(Qsb[r2loc * FKP + k0 + tig]);
            uint32_t a2 = __float_as_uint(Qsb[r1loc * FKP + k0 + tig + 4]);
            uint32_t a3 = __float_as_uint(Qsb[r2loc * FKP + k0 + tig + 4]);
#pragma unroll
            for (int nb = 0; nb < 8; nb++) {
                uint32_t b0 = __float_as_uint(Ksb[(nb * 8 + gid) * FKP + k0 + tig]);
                uint32_t b1 = __float_as_uint(Ksb[(nb * 8 + gid) * FKP + k0 + tig + 4]);
                mma_tf32(sacc[nb][0], sacc[nb][1], sacc[nb][2], sacc[nb][3],
                         a0, a1, a2, a3, b0, b1);
            }
        }

        // causal mask
        if (j >= 2 * qt) {
#pragma unroll
            for (int nb = 0; nb < 8; nb++) {
                int c0g = j * 64 + nb * 8 + tig * 2;
                if (c0g > r1g)     sacc[nb][0] = -1e30f;
                if (c0g + 1 > r1g) sacc[nb][1] = -1e30f;
                if (c0g > r2g)     sacc[nb][2] = -1e30f;
                if (c0g + 1 > r2g) sacc[nb][3] = -1e30f;
            }
        }

        // row max over quad
        float mx1 = -1e30f, mx2 = -1e30f;
#pragma unroll
        for (int nb = 0; nb < 8; nb++) {
            mx1 = fmaxf(mx1, fmaxf(sacc[nb][0], sacc[nb][1]));
            mx2 = fmaxf(mx2, fmaxf(sacc[nb][2], sacc[nb][3]));
        }
        mx1 = fmaxf(mx1, __shfl_xor_sync(0xffffffffu, mx1, 1));
        mx1 = fmaxf(mx1, __shfl_xor_sync(0xffffffffu, mx1, 2));
        mx2 = fmaxf(mx2, __shfl_xor_sync(0xffffffffu, mx2, 1));
        mx2 = fmaxf(mx2, __shfl_xor_sync(0xffffffffu, mx2, 2));

        float mn1 = fmaxf(m1, mx1), mn2 = fmaxf(m2, mx2);
        // warp-uniform skip: if no row in this warp raised its max, f == 1 exactly
        const bool changed = (mn1 != m1) | (mn2 != m2);
        const bool any_changed = __any_sync(0xffffffffu, changed);
        float f1 = 1.f, f2 = 1.f;
        if (any_changed) {
            f1 = exp2f(m1 - mn1);
            f2 = exp2f(m2 - mn2);
        }
        m1 = mn1; m2 = mn2;

        // probs (tf32-rounded, kept in sacc) + row sums
        float ls1 = 0.f, ls2 = 0.f;
#pragma unroll
        for (int nb = 0; nb < 8; nb++) {
            float p0 = tf32r(exp2f(sacc[nb][0] - mn1));
            float p1 = tf32r(exp2f(sacc[nb][1] - mn1));
            float p2 = tf32r(exp2f(sacc[nb][2] - mn2));
            float p3 = tf32r(exp2f(sacc[nb][3] - mn2));
            sacc[nb][0] = p0; sacc[nb][1] = p1;
            sacc[nb][2] = p2; sacc[nb][3] = p3;
            ls1 += p0 + p1;
            ls2 += p2 + p3;
        }
        ls1 += __shfl_xor_sync(0xffffffffu, ls1, 1);
        ls1 += __shfl_xor_sync(0xffffffffu, ls1, 2);
        ls2 += __shfl_xor_sync(0xffffffffu, ls2, 1);
        ls2 += __shfl_xor_sync(0xffffffffu, ls2, 2);

        if (any_changed) {
            l1 = l1 * f1 + ls1;
            l2 = l2 * f2 + ls2;
#pragma unroll
            for (int db = 0; db < 16; db++) {
                oacc[db][0] *= f1; oacc[db][1] *= f1;
                oacc[db][2] *= f2; oacc[db][3] *= f2;
            }
        } else {
            l1 += ls1;
            l2 += ls2;
        }

        // O += P @ V  (A-frag from sacc via quad shfls)
        const int s2 = tig >> 1;
        const bool odd = (tig & 1);
#pragma unroll
        for (int ks = 0; ks < 8; ks++) {
            float e, o;
            e = __shfl_sync(0xffffffffu, sacc[ks][0], s2, 4);
            o = __shfl_sync(0xffffffffu, sacc[ks][1], s2, 4);
            float a0f = odd ? o : e;
            e = __shfl_sync(0xffffffffu, sacc[ks][0], s2 + 2, 4);
            o = __shfl_sync(0xffffffffu, sacc[ks][1], s2 + 2, 4);
            float a2f = odd ? o : e;
            e = __shfl_sync(0xffffffffu, sacc[ks][2], s2, 4);
            o = __shfl_sync(0xffffffffu, sacc[ks][3], s2, 4);
            float a1f = odd ? o : e;
            e = __shfl_sync(0xffffffffu, sacc[ks][2], s2 + 2, 4);
            o = __shfl_sync(0xffffffffu, sacc[ks][3], s2 + 2, 4);
            float a3f = odd ? o : e;

            uint32_t a0 = __float_as_uint(a0f);
            uint32_t a1 = __float_as_uint(a1f);
            uint32_t a2 = __float_as_uint(a2f);
            uint32_t a3 = __float_as_uint(a3f);
            int k0 = ks * 8;
#pragma unroll
            for (int db = 0; db < 16; db++) {
                uint32_t b0 = __float_as_uint(Vsb[(db * 8 + gid) * FVP + k0 + tig]);
                uint32_t b1 = __float_as_uint(Vsb[(db * 8 + gid) * FVP + k0 + tig + 4]);
                mma_tf32(oacc[db][0], oacc[db][1], oacc[db][2], oacc[db][3],
                         a0, a1, a2, a3, b0, b1);
            }
        }
    }

    // epilogue: normalize, tf32-round (feeds O-proj GEMM), write
    const float inv1 = 1.0f / l1, inv2 = 1.0f / l2;
    const size_t obase = ((size_t)(b * S_ + qt * 128)) * (NH * DH) + (size_t)h * DH;
#pragma unroll
    for (int db = 0; db < 16; db++) {
        int c = db * 8 + tig * 2;
        *(float2*)(Og + obase + (size_t)r1loc * (NH * DH) + c) =
            make_float2(tf32r(oacc[db][0] * inv1), tf32r(oacc[db][1] * inv1));
        *(float2*)(Og + obase + (size_t)r2loc * (NH * DH) + c) =
            make_float2(tf32r(oacc[db][2] * inv2), tf32r(oacc[db][3] * inv2));
    }
}

// ---------------- launch ----------------
extern "C" void kernel_launch(void* const* d_in, const int* in_sizes, int n_in,
                              void* d_out, int out_size)
{
    const float* X    = (const float*)d_in[0];
    // d_in[1] = attention_mask: exact causal mask, applied analytically — unused
    const float* cosp = (const float*)d_in[2];
    const float* sinp = (const float*)d_in[3];
    const float* Wq   = (const float*)d_in[4];
    const float* Wk   = (const float*)d_in[5];
    const float* Wv   = (const float*)d_in[6];
    const float* Wo   = (const float*)d_in[7];
    const float* qnw  = (const float*)d_in[8];
    const float* knw  = (const float*)d_in[9];
    float* out = (float*)d_out;

    float *Xr, *QKV, *VtP, *O, *WqkvT, *WoT;
    cudaGetSymbolAddress((void**)&Xr,    g_X);
    cudaGetSymbolAddress((void**)&QKV,   g_QKV);
    cudaGetSymbolAddress((void**)&VtP,   g_Vt);
    cudaGetSymbolAddress((void**)&O,     g_O);
    cudaGetSymbolAddress((void**)&WqkvT, g_WqkvT);
    cudaGetSymbolAddress((void**)&WoT,   g_WoT);

    cudaFuncSetAttribute(gemm_tf32mma_kernel, cudaFuncAttributeMaxDynamicSharedMemorySize,
                         GM_SMEM_BYTES);
    cudaFuncSetAttribute(flash_tc3_kernel, cudaFuncAttributeMaxDynamicSharedMemorySize,
                         FT_BYTES);

    // tf32-round X; transpose+round weights into packed WqkvT [3072][2048]
    tf32_round_kernel<<<2048, 256>>>(Xr, X, (size_t)MROWS * HID / 4);
    transpose_tf32_kernel<<<dim3((NH * DH) / 32, HID / 32), dim3(32, 8)>>>(
        WqkvT, Wq, HID, NH * DH);
    transpose_tf32_kernel<<<dim3((NKV * DH) / 32, HID / 32), dim3(32, 8)>>>(
        WqkvT + (size_t)KOFF * HID, Wk, HID, NKV * DH);
    transpose_tf32_kernel<<<dim3((NKV * DH) / 32, HID / 32), dim3(32, 8)>>>(
        WqkvT + (size_t)VOFF * HID, Wv, HID, NKV * DH);
    transpose_tf32_kernel<<<dim3(HID / 32, (NH * DH) / 32), dim3(32, 8)>>>(
        WoT, Wo, NH * DH, HID);

    // Fused QKV projection: one GEMM, N=3072, packed output
    gemm_tf32mma_kernel<<<dim3(QKVS / GM_BN, MROWS / GM_BM), 256, GM_SMEM_BYTES>>>(
        Xr, WqkvT, QKV, MROWS, QKVS);

    // RMSNorm + RoPE in place on the packed buffer
    rmsrope_kernel<<<MROWS * NH, 128>>>(QKV, qnw, cosp, sinp, NH, SCL2E, QKVS, 0);
    rmsrope_kernel<<<MROWS * NKV, 128>>>(QKV, knw, cosp, sinp, NKV, 1.0f, QKVS, KOFF);
    vtrans_kernel<<<dim3(S_ / 32, DH / 32, B_ * NKV), dim3(32, 8)>>>(VtP, QKV);

    // Flash attention v3
    flash_tc3_kernel<<<dim3(S_ / 128, NH, B_), 256, FT_BYTES>>>(QKV, VtP, O);

    // O-projection
    gemm_tf32mma_kernel<<<dim3(HID / GM_BN, MROWS / GM_BM), 256, GM_SMEM_BYTES>>>(
        O, WoT, out, MROWS, HID);
}

// round 10
// speedup vs baseline: 3.4356x; 1.0355x over previous
#include <cuda_runtime.h>
#include <cuda_bf16.h>
#include <math.h>
#include <stdint.h>

// Problem constants
#define B_  2
#define S_  2048
#define HID 2048
#define NH  16
#define NKV 4
#define DH  128
#define MROWS (B_ * S_)        // 4096
#define EPS 1e-6f

// packed QKV layout: [row][ Q(0..2047) | K(2048..2559) | V(2560..3071) ]
#define QKVS 3072
#define KOFF 2048
#define VOFF 2560

// 1/sqrt(DH) * log2(e): folded into Q during rmsrope; softmax uses exp2f.
#define SCL2E (0.08838834764831845f * 1.4426950408889634f)

// K-dim fragment interleave: within each 8-group, q -> 2*(q&3) + (q>>2).
// Makes mma.sync fragment pairs (q, q+4) physically adjacent -> LDS.64.
__device__ __host__ __forceinline__ int perm8(int q) { return 2 * (q & 3) + (q >> 2); }

// ---------------- scratch ----------------
__device__ float g_X   [(size_t)MROWS * HID];        // Xr (K-permuted); later reused as Qp
__device__ float g_QKV [(size_t)MROWS * QKVS];       // packed Q|K|V (normal layout)
__device__ float g_Kp  [(size_t)MROWS * NKV * DH];   // K, rmsnorm+rope'd, d-permuted
__device__ float g_Vt  [(size_t)B_ * NKV * DH * S_]; // [b][kvh][d][s], s-permuted, tf32
__device__ float g_O   [(size_t)MROWS * NH * DH];    // flash out, d-permuted
__device__ float g_WqkvT[(size_t)QKVS * HID];        // [N=3072][K=2048], K-permuted
__device__ float g_WoT [(size_t)NH * DH * HID];      // [N=2048][K=2048], K-permuted

// ---------------- helpers ----------------
__device__ __forceinline__ uint32_t smem_u32(const void* p) {
    uint32_t a;
    asm("{ .reg .u64 t; cvta.to.shared.u64 t, %1; cvt.u32.u64 %0, t; }" : "=r"(a) : "l"(p));
    return a;
}
__device__ __forceinline__ float tf32r(float x) {
    uint32_t r;
    asm("cvt.rna.tf32.f32 %0, %1;" : "=r"(r) : "f"(x));
    return __uint_as_float(r);
}
#define CP_ASYNC16(sdst, gsrc) \
    asm volatile("cp.async.cg.shared.global [%0], [%1], 16;" :: "r"(sdst), "l"(gsrc))
#define CP_COMMIT() asm volatile("cp.async.commit_group;" ::: "memory")
#define CP_WAIT(n)  asm volatile("cp.async.wait_group %0;" :: "n"(n) : "memory")

__device__ __forceinline__ void mma_tf32(float& c0, float& c1, float& c2, float& c3,
                                         uint32_t a0, uint32_t a1, uint32_t a2, uint32_t a3,
                                         uint32_t b0, uint32_t b1) {
    asm volatile(
        "mma.sync.aligned.m16n8k8.row.col.f32.tf32.tf32.f32 "
        "{%0,%1,%2,%3}, {%4,%5,%6,%7}, {%8,%9}, {%0,%1,%2,%3};"
        : "+f"(c0), "+f"(c1), "+f"(c2), "+f"(c3)
        : "r"(a0), "r"(a1), "r"(a2), "r"(a3), "r"(b0), "r"(b1));
}

// ---------------- X: tf32 round + K-dim interleave (vectorized) ----------------
// dst 8-group {0..7} = src {0,4,1,5,2,6,3,7}
__global__ void __launch_bounds__(256) xperm_tf32_kernel(float* __restrict__ dst,
                                                         const float* __restrict__ src,
                                                         size_t n8) {   // # of 8-float groups
    for (size_t i = blockIdx.x * blockDim.x + threadIdx.x; i < n8;
         i += (size_t)gridDim.x * blockDim.x) {
        float4 lo = ((const float4*)src)[i * 2];
        float4 hi = ((const float4*)src)[i * 2 + 1];
        float4 o0 = make_float4(tf32r(lo.x), tf32r(hi.x), tf32r(lo.y), tf32r(hi.y));
        float4 o1 = make_float4(tf32r(lo.z), tf32r(hi.z), tf32r(lo.w), tf32r(hi.w));
        ((float4*)dst)[i * 2]     = o0;
        ((float4*)dst)[i * 2 + 1] = o1;
    }
}

// ---------------- transpose + tf32 round + K-permute: dst[C][R'] ----------------
// dst[n][perm(k)] = tf32(src[k][n]);  dst col index (by+tx) permuted within 8-groups.
__global__ void __launch_bounds__(256) transpose_tf32_kernel(float* __restrict__ dst,
                                                             const float* __restrict__ src,
                                                             int R, int C) {
    __shared__ float t[32][33];
    int bx = blockIdx.x * 32;
    int by = blockIdx.y * 32;
    int tx = threadIdx.x, ty = threadIdx.y;
#pragma unroll
    for (int i = 0; i < 4; i++)
        t[ty + i * 8][tx] = src[(size_t)(by + ty + i * 8) * C + bx + tx];
    __syncthreads();
    int px = (tx & 24) + perm8(tx & 7);
#pragma unroll
    for (int i = 0; i < 4; i++)
        dst[(size_t)(bx + ty + i * 8) * R + by + px] = tf32r(t[tx][ty + i * 8]);
}

// ---------------- V transpose from packed QKV -> g_Vt [b][kvh][d][s'] (tf32) ----------------
// s (kv position, the PV reduction dim) permuted within 8-groups.
__global__ void __launch_bounds__(256) vtrans_kernel(float* __restrict__ dst,
                                                     const float* __restrict__ src) {
    __shared__ float t[32][33];
    const int bz = blockIdx.z;              // b*NKV + kvh
    const int b = bz >> 2, kvh = bz & 3;
    const int s0 = blockIdx.x * 32, d0 = blockIdx.y * 32;
    const int tx = threadIdx.x, ty = threadIdx.y;   // 32 x 8
#pragma unroll
    for (int i = 0; i < 4; i++)
        t[ty + i * 8][tx] =
            src[(size_t)(b * S_ + s0 + ty + i * 8) * QKVS + VOFF + kvh * DH + d0 + tx];
    __syncthreads();
    int px = (tx & 24) + perm8(tx & 7);
#pragma unroll
    for (int i = 0; i < 4; i++)
        dst[((size_t)bz * DH + d0 + ty + i * 8) * S_ + s0 + px] = tf32r(t[tx][ty + i * 8]);
}

// ---------------- tf32 mma.sync GEMM (K-permuted operands, LDS.64 fragments) ----------------
#define GK      2048
#define GM_BM   128
#define GM_BN   128
#define GM_BK   16
#define GM_LDS  24                           // mod 32 = 24: conflict-free LDS.64 phases
#define GM_NST  3
#define GM_NIT  (GK / GM_BK)
#define GM_STAGE_FLOATS (2 * 128 * GM_LDS)   // 6144
#define GM_SMEM_BYTES (GM_NST * GM_STAGE_FLOATS * 4)   // 73728

__device__ __forceinline__ void gm_load_stage(uint32_t sA, uint32_t sB,
                                              const float* __restrict__ Atile,
                                              const float* __restrict__ Btile,
                                              int tid) {
#pragma unroll
    for (int i = 0; i < 2; i++) {
        int idx = i * 256 + tid;
        int r = idx >> 2, c = idx & 3;
        CP_ASYNC16(sA + (uint32_t)(r * (GM_LDS * 4) + c * 16),
                   Atile + (size_t)r * GK + c * 4);
    }
#pragma unroll
    for (int i = 0; i < 2; i++) {
        int idx = i * 256 + tid;
        int r = idx >> 2, c = idx & 3;
        CP_ASYNC16(sB + (uint32_t)(r * (GM_LDS * 4) + c * 16),
                   Btile + (size_t)r * GK + c * 4);
    }
    CP_COMMIT();
}

__global__ void __launch_bounds__(256, 1) gemm_tf32mma_kernel(
    const float* __restrict__ A, const float* __restrict__ Bt,
    float* __restrict__ C, int M, int N)
{
    extern __shared__ float gsm[];
    const uint32_t sbase = smem_u32(gsm);
    const int tid = threadIdx.x;
    const int wid = tid >> 5, lid = tid & 31;
    const int wm = wid >> 1;
    const int wn = wid & 1;
    const int gid = lid >> 2;
    const int tig = lid & 3;
    const int bm = blockIdx.y * GM_BM;
    const int bn = blockIdx.x * GM_BN;

    float acc[2][8][4];
#pragma unroll
    for (int mt = 0; mt < 2; mt++)
#pragma unroll
        for (int nt = 0; nt < 8; nt++)
#pragma unroll
            for (int q = 0; q < 4; q++) acc[mt][nt][q] = 0.f;

    const float* Abase = A + (size_t)bm * GK;
    const float* Bbase = Bt + (size_t)bn * GK;

    uint32_t stA[GM_NST], stB[GM_NST];
#pragma unroll
    for (int s = 0; s < GM_NST; s++) {
        stA[s] = sbase + (uint32_t)(s * GM_STAGE_FLOATS * 4);
        stB[s] = stA[s] + 128u * GM_LDS * 4u;
    }

    gm_load_stage(stA[0], stB[0], Abase, Bbase, tid);
    gm_load_stage(stA[1], stB[1], Abase + GM_BK, Bbase + GM_BK, tid);

    const float* As0;
    const float* Bs0;

    for (int it = 0; it < GM_NIT; it++) {
        CP_WAIT(1);
        __syncthreads();

        const int ki = it + 2;
        if (ki < GM_NIT) {
            const int b = ki % GM_NST;
            gm_load_stage(stA[b], stB[b], Abase + ki * GM_BK, Bbase + ki * GM_BK, tid);
        }

        const int s = it % GM_NST;
        As0 = gsm + (size_t)s * GM_STAGE_FLOATS;
        Bs0 = As0 + 128 * GM_LDS;

#pragma unroll
        for (int k0 = 0; k0 < GM_BK; k0 += 8) {
            uint32_t af[2][4];
#pragma unroll
            for (int mt = 0; mt < 2; mt++) {
                int r = wm * 32 + mt * 16 + gid;
                float2 aA = *(const float2*)(As0 + r * GM_LDS + k0 + 2 * tig);
                float2 aB = *(const float2*)(As0 + (r + 8) * GM_LDS + k0 + 2 * tig);
                af[mt][0] = __float_as_uint(aA.x);
                af[mt][1] = __float_as_uint(aB.x);
                af[mt][2] = __float_as_uint(aA.y);
                af[mt][3] = __float_as_uint(aB.y);
            }
#pragma unroll
            for (int nt = 0; nt < 8; nt++) {
                int rn = wn * 64 + nt * 8 + gid;
                float2 bv = *(const float2*)(Bs0 + rn * GM_LDS + k0 + 2 * tig);
                uint32_t b0 = __float_as_uint(bv.x);
                uint32_t b1 = __float_as_uint(bv.y);
#pragma unroll
                for (int mt = 0; mt < 2; mt++)
                    mma_tf32(acc[mt][nt][0], acc[mt][nt][1], acc[mt][nt][2], acc[mt][nt][3],
                             af[mt][0], af[mt][1], af[mt][2], af[mt][3], b0, b1);
            }
        }
    }

#pragma unroll
    for (int mt = 0; mt < 2; mt++) {
        int r0 = bm + wm * 32 + mt * 16 + gid;
#pragma unroll
        for (int nt = 0; nt < 8; nt++) {
            int c = bn + wn * 64 + nt * 8 + tig * 2;
            float2 v0 = make_float2(acc[mt][nt][0], acc[mt][nt][1]);
            float2 v1 = make_float2(acc[mt][nt][2], acc[mt][nt][3]);
            *(float2*)(C + (size_t)r0 * N + c)       = v0;
            *(float2*)(C + (size_t)(r0 + 8) * N + c) = v1;
        }
    }
}

// ---------------- fused RMSNorm + RoPE (reads packed QKV; writes d-permuted) ----------------
__global__ void __launch_bounds__(128) rmsrope_kernel(
    const float* __restrict__ inbuf, float* __restrict__ outbuf,
    const float* __restrict__ w,
    const float* __restrict__ cosb, const float* __restrict__ sinb, int nheads,
    float oscale, int in_hoff, int outstride)
{
    const int bh  = blockIdx.x;
    const int row = bh / nheads;
    const int h   = bh - row * nheads;
    const int s   = row & (S_ - 1);
    const int d   = threadIdx.x;

    const float* p = inbuf + (size_t)row * QKVS + in_hoff + h * DH;
    float v = p[d];

    float ss = v * v;
#pragma unroll
    for (int o = 16; o > 0; o >>= 1) ss += __shfl_xor_sync(0xffffffffu, ss, o);
    __shared__ float sh[4];
    if ((d & 31) == 0) sh[d >> 5] = ss;
    __syncthreads();
    float tot = sh[0] + sh[1] + sh[2] + sh[3];
    float inv = rsqrtf(tot * (1.0f / DH) + EPS);

    int pd = d ^ 64;
    float pv  = p[pd];
    float nv  = w[d]  * v  * inv;
    float npv = w[pd] * pv * inv;
    float c  = cosb[(size_t)s * DH + d];
    float sn = sinb[(size_t)s * DH + d];
    float out = nv * c + ((d < 64) ? -npv : npv) * sn;

    int dp = (d & ~7) + perm8(d & 7);
    outbuf[(size_t)row * outstride + h * DH + dp] = tf32r(out * oscale);
}

// ---------------- tensor-core flash attention v4 (LDS.64 fragments) ----------------
// Q from g_X (d-permuted, stride 2048); K from g_Kp (d-permuted, stride 512);
// V from g_Vt (s-permuted). Output O d-permuted (feeds K-permuted O-proj).
#define FKP 136                              // mod 32 = 8: conflict-free LDS.64
#define FVP 72
#define FQ_OFF 0
#define FK_OFF (128 * FKP)                   // 17408 floats
#define FV_OFF (FK_OFF + 2 * 64 * FKP)       // 34816 floats
#define FT_FLOATS (FV_OFF + 2 * 128 * FVP)   // 53248 floats
#define FT_BYTES (FT_FLOATS * 4)             // 212992 bytes

__global__ void __launch_bounds__(256, 1) flash_tc4_kernel(
    const float* __restrict__ Qp, const float* __restrict__ Kp,
    const float* __restrict__ Vt, float* __restrict__ Og)
{
    extern __shared__ float fsm[];
    const uint32_t sb = smem_u32(fsm);

    const int qt  = (int)gridDim.x - 1 - (int)blockIdx.x;   // long blocks first
    const int h   = blockIdx.y;
    const int b   = blockIdx.z;
    const int kvh = h >> 2;
    const int tid = threadIdx.x;
    const int wid = tid >> 5, lid = tid & 31;
    const int gid = lid >> 2, tig = lid & 3;

    const int r1loc = wid * 16 + gid;
    const int r2loc = r1loc + 8;
    const int r1g = qt * 128 + r1loc;
    const int r2g = r1g + 8;

    const float* Kbase  = Kp + (size_t)(b * S_) * (NKV * DH) + (size_t)kvh * DH;
    const float* Vtbase = Vt + ((size_t)(b * NKV + kvh) * DH) * S_;

    // Q tile: 128 rows x 32 float4-chunks
    {
        const float* Qb = Qp + (size_t)(b * S_ + qt * 128) * HID + (size_t)h * DH;
#pragma unroll
        for (int t = 0; t < 16; t++) {
            int i = tid + t * 256;
            int m = i >> 5, c = i & 31;
            CP_ASYNC16(sb + (uint32_t)((FQ_OFF + m * FKP + c * 4) * 4),
                       Qb + (size_t)m * HID + c * 4);
        }
    }
    // K tile 0: 64 rows x 32 chunks
#pragma unroll
    for (int t = 0; t < 8; t++) {
        int i = tid + t * 256;
        int n = i >> 5, c = i & 31;
        CP_ASYNC16(sb + (uint32_t)((FK_OFF + n * FKP + c * 4) * 4),
                   Kbase + (size_t)n * (NKV * DH) + c * 4);
    }
    // V tile 0: 128 d-rows x 16 chunks
#pragma unroll
    for (int t = 0; t < 8; t++) {
        int i = tid + t * 256;
        int d = i >> 4, c = i & 15;
        CP_ASYNC16(sb + (uint32_t)((FV_OFF + d * FVP + c * 4) * 4),
                   Vtbase + (size_t)d * S_ + c * 4);
    }
    CP_COMMIT();

    float oacc[16][4];
#pragma unroll
    for (int db = 0; db < 16; db++)
#pragma unroll
        for (int q = 0; q < 4; q++) oacc[db][q] = 0.f;
    float m1 = -1e30f, m2 = -1e30f, l1 = 0.f, l2 = 0.f;

    const int ntiles = 2 * qt + 2;
    for (int j = 0; j < ntiles; j++) {
        CP_WAIT(0);
        __syncthreads();

        // prefetch tile j+1 into the other buffer
        if (j + 1 < ntiles) {
            const int nb_ = (j + 1) & 1;
            const uint32_t kd = sb + (uint32_t)((FK_OFF + nb_ * 64 * FKP) * 4);
            const uint32_t vd = sb + (uint32_t)((FV_OFF + nb_ * 128 * FVP) * 4);
#pragma unroll
            for (int t = 0; t < 8; t++) {
                int i = tid + t * 256;
                int n = i >> 5, c = i & 31;
                CP_ASYNC16(kd + (uint32_t)((n * FKP + c * 4) * 4),
                           Kbase + (size_t)((j + 1) * 64 + n) * (NKV * DH) + c * 4);
            }
#pragma unroll
            for (int t = 0; t < 8; t++) {
                int i = tid + t * 256;
                int d = i >> 4, c = i & 15;
                CP_ASYNC16(vd + (uint32_t)((d * FVP + c * 4) * 4),
                           Vtbase + (size_t)d * S_ + (j + 1) * 64 + c * 4);
            }
            CP_COMMIT();
        }

        const float* Qsb = fsm;
        const float* Ksb = fsm + FK_OFF + (j & 1) * 64 * FKP;
        const float* Vsb = fsm + FV_OFF + (j & 1) * 128 * FVP;

        // S = Q @ K^T  (fragment pairs via LDS.64 on permuted layout)
        float sacc[8][4];
#pragma unroll
        for (int nb = 0; nb < 8; nb++)
#pragma unroll
            for (int q = 0; q < 4; q++) sacc[nb][q] = 0.f;

#pragma unroll
        for (int ks = 0; ks < 16; ks++) {
            int k0 = ks * 8;
            float2 qa = *(const float2*)(Qsb + r1loc * FKP + k0 + 2 * tig);
            float2 qb = *(const float2*)(Qsb + r2loc * FKP + k0 + 2 * tig);
            uint32_t a0 = __float_as_uint(qa.x);
            uint32_t a1 = __float_as_uint(qb.x);
            uint32_t a2 = __float_as_uint(qa.y);
            uint32_t a3 = __float_as_uint(qb.y);
#pragma unroll
            for (int nb = 0; nb < 8; nb++) {
                float2 kv2 = *(const float2*)(Ksb + (nb * 8 + gid) * FKP + k0 + 2 * tig);
                mma_tf32(sacc[nb][0], sacc[nb][1], sacc[nb][2], sacc[nb][3],
                         a0, a1, a2, a3,
                         __float_as_uint(kv2.x), __float_as_uint(kv2.y));
            }
        }

        // causal mask
        if (j >= 2 * qt) {
#pragma unroll
            for (int nb = 0; nb < 8; nb++) {
                int c0g = j * 64 + nb * 8 + tig * 2;
                if (c0g > r1g)     sacc[nb][0] = -1e30f;
                if (c0g + 1 > r1g) sacc[nb][1] = -1e30f;
                if (c0g > r2g)     sacc[nb][2] = -1e30f;
                if (c0g + 1 > r2g) sacc[nb][3] = -1e30f;
            }
        }

        // row max over quad
        float mx1 = -1e30f, mx2 = -1e30f;
#pragma unroll
        for (int nb = 0; nb < 8; nb++) {
            mx1 = fmaxf(mx1, fmaxf(sacc[nb][0], sacc[nb][1]));
            mx2 = fmaxf(mx2, fmaxf(sacc[nb][2], sacc[nb][3]));
        }
        mx1 = fmaxf(mx1, __shfl_xor_sync(0xffffffffu, mx1, 1));
        mx1 = fmaxf(mx1, __shfl_xor_sync(0xffffffffu, mx1, 2));
        mx2 = fmaxf(mx2, __shfl_xor_sync(0xffffffffu, mx2, 1));
        mx2 = fmaxf(mx2, __shfl_xor_sync(0xffffffffu, mx2, 2));

        float mn1 = fmaxf(m1, mx1), mn2 = fmaxf(m2, mx2);
        const bool changed = (mn1 != m1) | (mn2 != m2);
        const bool any_changed = __any_sync(0xffffffffu, changed);
        float f1 = 1.f, f2 = 1.f;
        if (any_changed) {
            f1 = exp2f(m1 - mn1);
            f2 = exp2f(m2 - mn2);
        }
        m1 = mn1; m2 = mn2;

        // probs + row sums
        float ls1 = 0.f, ls2 = 0.f;
#pragma unroll
        for (int nb = 0; nb < 8; nb++) {
            float p0 = tf32r(exp2f(sacc[nb][0] - mn1));
            float p1 = tf32r(exp2f(sacc[nb][1] - mn1));
            float p2 = tf32r(exp2f(sacc[nb][2] - mn2));
            float p3 = tf32r(exp2f(sacc[nb][3] - mn2));
            sacc[nb][0] = p0; sacc[nb][1] = p1;
            sacc[nb][2] = p2; sacc[nb][3] = p3;
            ls1 += p0 + p1;
            ls2 += p2 + p3;
        }
        ls1 += __shfl_xor_sync(0xffffffffu, ls1, 1);
        ls1 += __shfl_xor_sync(0xffffffffu, ls1, 2);
        ls2 += __shfl_xor_sync(0xffffffffu, ls2, 1);
        ls2 += __shfl_xor_sync(0xffffffffu, ls2, 2);

        if (any_changed) {
            l1 = l1 * f1 + ls1;
            l2 = l2 * f2 + ls2;
#pragma unroll
            for (int db = 0; db < 16; db++) {
                oacc[db][0] *= f1; oacc[db][1] *= f1;
                oacc[db][2] *= f2; oacc[db][3] *= f2;
            }
        } else {
            l1 += ls1;
            l2 += ls2;
        }

        // O += P @ V  (A-frag from sacc via quad shfls; V b-pairs via LDS.64)
        const int s2 = tig >> 1;
        const bool odd = (tig & 1);
#pragma unroll
        for (int ks = 0; ks < 8; ks++) {
            float e, o;
            e = __shfl_sync(0xffffffffu, sacc[ks][0], s2, 4);
            o = __shfl_sync(0xffffffffu, sacc[ks][1], s2, 4);
            float a0f = odd ? o : e;
            e = __shfl_sync(0xffffffffu, sacc[ks][0], s2 + 2, 4);
            o = __shfl_sync(0xffffffffu, sacc[ks][1], s2 + 2, 4);
            float a2f = odd ? o : e;
            e = __shfl_sync(0xffffffffu, sacc[ks][2], s2, 4);
            o = __shfl_sync(0xffffffffu, sacc[ks][3], s2, 4);
            float a1f = odd ? o : e;
            e = __shfl_sync(0xffffffffu, sacc[ks][2], s2 + 2, 4);
            o = __shfl_sync(0xffffffffu, sacc[ks][3], s2 + 2, 4);
            float a3f = odd ? o : e;

            uint32_t a0 = __float_as_uint(a0f);
            uint32_t a1 = __float_as_uint(a1f);
            uint32_t a2 = __float_as_uint(a2f);
            uint32_t a3 = __float_as_uint(a3f);
            int k0 = ks * 8;
#pragma unroll
            for (int db = 0; db < 16; db++) {
                float2 vv = *(const float2*)(Vsb + (db * 8 + gid) * FVP + k0 + 2 * tig);
                mma_tf32(oacc[db][0], oacc[db][1], oacc[db][2], oacc[db][3],
                         a0, a1, a2, a3,
                         __float_as_uint(vv.x), __float_as_uint(vv.y));
            }
        }
    }

    // epilogue: normalize, tf32-round, write d-PERMUTED (input to K-permuted O-proj)
    const float inv1 = 1.0f / l1, inv2 = 1.0f / l2;
    const size_t obase = ((size_t)(b * S_ + qt * 128)) * (NH * DH) + (size_t)h * DH;
    const int p0 = perm8(2 * tig);       // physical position of logical col 2*tig
    const int p1 = perm8(2 * tig + 1);
#pragma unroll
    for (int db = 0; db < 16; db++) {
        float* o1p = Og + obase + (size_t)r1loc * (NH * DH) + db * 8;
        float* o2p = Og + obase + (size_t)r2loc * (NH * DH) + db * 8;
        o1p[p0] = tf32r(oacc[db][0] * inv1);
        o1p[p1] = tf32r(oacc[db][1] * inv1);
        o2p[p0] = tf32r(oacc[db][2] * inv2);
        o2p[p1] = tf32r(oacc[db][3] * inv2);
    }
}

// ---------------- launch ----------------
extern "C" void kernel_launch(void* const* d_in, const int* in_sizes, int n_in,
                              void* d_out, int out_size)
{
    const float* X    = (const float*)d_in[0];
    // d_in[1] = attention_mask: exact causal mask, applied analytically — unused
    const float* cosp = (const float*)d_in[2];
    const float* sinp = (const float*)d_in[3];
    const float* Wq   = (const float*)d_in[4];
    const float* Wk   = (const float*)d_in[5];
    const float* Wv   = (const float*)d_in[6];
    const float* Wo   = (const float*)d_in[7];
    const float* qnw  = (const float*)d_in[8];
    const float* knw  = (const float*)d_in[9];
    float* out = (float*)d_out;

    float *Xr, *QKV, *Kp, *VtP, *O, *WqkvT, *WoT;
    cudaGetSymbolAddress((void**)&Xr,    g_X);
    cudaGetSymbolAddress((void**)&QKV,   g_QKV);
    cudaGetSymbolAddress((void**)&Kp,    g_Kp);
    cudaGetSymbolAddress((void**)&VtP,   g_Vt);
    cudaGetSymbolAddress((void**)&O,     g_O);
    cudaGetSymbolAddress((void**)&WqkvT, g_WqkvT);
    cudaGetSymbolAddress((void**)&WoT,   g_WoT);

    cudaFuncSetAttribute(gemm_tf32mma_kernel, cudaFuncAttributeMaxDynamicSharedMemorySize,
                         GM_SMEM_BYTES);
    cudaFuncSetAttribute(flash_tc4_kernel, cudaFuncAttributeMaxDynamicSharedMemorySize,
                         FT_BYTES);

    // X: tf32 round + K-permute; weights: transpose + round + K-permute
    xperm_tf32_kernel<<<2048, 256>>>(Xr, X, (size_t)MROWS * HID / 8);
    transpose_tf32_kernel<<<dim3((NH * DH) / 32, HID / 32), dim3(32, 8)>>>(
        WqkvT, Wq, HID, NH * DH);
    transpose_tf32_kernel<<<dim3((NKV * DH) / 32, HID / 32), dim3(32, 8)>>>(
        WqkvT + (size_t)KOFF * HID, Wk, HID, NKV * DH);
    transpose_tf32_kernel<<<dim3((NKV * DH) / 32, HID / 32), dim3(32, 8)>>>(
        WqkvT + (size_t)VOFF * HID, Wv, HID, NKV * DH);
    transpose_tf32_kernel<<<dim3(HID / 32, (NH * DH) / 32), dim3(32, 8)>>>(
        WoT, Wo, NH * DH, HID);

    // Fused QKV projection (output in normal layout)
    gemm_tf32mma_kernel<<<dim3(QKVS / GM_BN, MROWS / GM_BM), 256, GM_SMEM_BYTES>>>(
        Xr, WqkvT, QKV, MROWS, QKVS);

    // RMSNorm + RoPE: Q -> g_X (reused; d-permuted, pre-scaled); K -> g_Kp (d-permuted)
    rmsrope_kernel<<<MROWS * NH, 128>>>(QKV, Xr, qnw, cosp, sinp, NH, SCL2E, 0, HID);
    rmsrope_kernel<<<MROWS * NKV, 128>>>(QKV, Kp, knw, cosp, sinp, NKV, 1.0f, KOFF,
                                         NKV * DH);
    vtrans_kernel<<<dim3(S_ / 32, DH / 32, B_ * NKV), dim3(32, 8)>>>(VtP, QKV);

    // Flash attention v4
    flash_tc4_kernel<<<dim3(S_ / 128, NH, B_), 256, FT_BYTES>>>(Xr, Kp, VtP, O);

    // O-projection (A = O, d-permuted by flash epilogue; B = WoT, K-permuted)
    gemm_tf32mma_kernel<<<dim3(HID / GM_BN, MROWS / GM_BM), 256, GM_SMEM_BYTES>>>(
        O, WoT, out, MROWS, HID);
}